// round 9
// baseline (speedup 1.0000x reference)
#include <cuda_runtime.h>

// ---------------------------------------------------------------------------
// MIND loss, fully fused, single kernel. R9 = R8 (+/- shift pairing) with an
// fp16x2 row-conv buffer:
//  - row stage computes in f32x2, converts once to fp16x2 (P,G) at store
//  - column 7-tap runs in fma.rn.f16x2; Dmin via min.f16x2 (1 inst/px-shift)
//  - buffer bytes halve: row STS and col LDS wavefronts drop ~2x
//  - both passes recompute identical quantized values -> max-trick stays
//    self-consistent (exp arg <= 0 guaranteed)
//  - 40 +/- pairs + 19 singles = 59 barrier intervals per pass
//  - in-kernel deterministic last-CTA reduction
// ---------------------------------------------------------------------------

typedef unsigned long long u64;
typedef unsigned int u32;

namespace {
constexpr int HIMG = 384;
constexpr int WIMG = 384;
constexpr int BATCH = 4;
constexpr int INNER = 370;          // 384 - 2*7
constexpr int TILE_H = 32;
constexpr int TILE_W = 64;
constexpr int RH = 47;              // img tile rows (q_r in [-7, 39])
constexpr int RW = 86;              // img tile cols (q_c in [-11, 74])
constexpr int IP = 87;              // img pitch in u64 (odd)
constexpr int BROWS = 42;           // buffer rows (q_r in [-3, 38])
constexpr int BP = 73;              // buffer pitch in b32 (odd)
constexpr int NTHREADS = 256;
constexpr int TILES_X = 6;
constexpr int TILES_Y = 12;
constexpr int NCTAS = BATCH * TILES_X * TILES_Y;   // 288 -> one wave @ occ 2
constexpr int SMEM_BYTES = RH * IP * 8 + 2 * BROWS * BP * 4;  // 57240 B
constexpr int NEVENTS = 59;                        // 40 pairs + 19 singles

constexpr double E98 = 0.32465246735834974;   // exp(-9/8)
constexpr double E48 = 0.60653065971263342;   // exp(-4/8)
constexpr double E18 = 0.88249690258459546;   // exp(-1/8)
constexpr double TPS = 25.132741228718345;    // 8*pi
constexpr float GX0 = (float)E98;
constexpr float GX1 = (float)E48;
constexpr float GX2 = (float)E18;             // center tap == 1
constexpr float GY0 = (float)(E98 / TPS);
constexpr float GY1 = (float)(E48 / TPS);
constexpr float GY2 = (float)(E18 / TPS);
constexpr float GY3 = (float)(1.0 / TPS);
}  // namespace

__device__ float g_partials[NCTAS];
__device__ unsigned int g_count = 0;

// ---- packed f32x2 helpers (sm_100+) ----
__device__ __forceinline__ u64 bcast2(float x) {
  u64 r; asm("mov.b64 %0,{%1,%1};" : "=l"(r) : "f"(x)); return r;
}
__device__ __forceinline__ void up2(u64 v, float& a, float& b) {
  asm("mov.b64 {%0,%1},%2;" : "=f"(a), "=f"(b) : "l"(v));
}
__device__ __forceinline__ u64 f2sub(u64 a, u64 b) {
  u64 r; asm("sub.rn.f32x2 %0,%1,%2;" : "=l"(r) : "l"(a), "l"(b)); return r;
}
__device__ __forceinline__ u64 f2mul(u64 a, u64 b) {
  u64 r; asm("mul.rn.f32x2 %0,%1,%2;" : "=l"(r) : "l"(a), "l"(b)); return r;
}
__device__ __forceinline__ u64 f2add(u64 a, u64 b) {
  u64 r; asm("add.rn.f32x2 %0,%1,%2;" : "=l"(r) : "l"(a), "l"(b)); return r;
}
__device__ __forceinline__ u64 f2fma(u64 a, u64 b, u64 c) {
  u64 r; asm("fma.rn.f32x2 %0,%1,%2,%3;" : "=l"(r) : "l"(a), "l"(b), "l"(c));
  return r;
}

// ---- packed f16x2 helpers ----
__device__ __forceinline__ u32 bch2(float x) {   // broadcast float -> f16x2
  u32 r; asm("cvt.rn.f16x2.f32 %0,%1,%1;" : "=r"(r) : "f"(x)); return r;
}
__device__ __forceinline__ u32 f2h2(u64 v) {     // f32x2 -> f16x2 (lo=P)
  float a, b; up2(v, a, b);
  u32 r; asm("cvt.rn.f16x2.f32 %0,%1,%2;" : "=r"(r) : "f"(b), "f"(a));
  return r;
}
__device__ __forceinline__ void h2up(u32 v, float& a, float& b) {
  asm("{\n\t.reg .b16 l,h;\n\tmov.b32 {l,h},%2;\n\t"
      "cvt.f32.f16 %0,l;\n\tcvt.f32.f16 %1,h;\n\t}"
      : "=f"(a), "=f"(b) : "r"(v));
}
__device__ __forceinline__ u32 h2mul(u32 a, u32 b) {
  u32 r; asm("mul.rn.f16x2 %0,%1,%2;" : "=r"(r) : "r"(a), "r"(b)); return r;
}
__device__ __forceinline__ u32 h2fma(u32 a, u32 b, u32 c) {
  u32 r; asm("fma.rn.f16x2 %0,%1,%2,%3;" : "=r"(r) : "r"(a), "r"(b), "r"(c));
  return r;
}
__device__ __forceinline__ u32 h2min(u32 a, u32 b) {
  u32 r; asm("min.f16x2 %0,%1,%2;" : "=r"(r) : "r"(a), "r"(b)); return r;
}
__device__ __forceinline__ u32 h2sub(u32 a, u32 b) {
  u32 r; asm("sub.rn.f16x2 %0,%1,%2;" : "=r"(r) : "r"(a), "r"(b)); return r;
}

// Event schedule. e<40: pair representatives (sy>0, or sy==0 && sx>=1);
// each also yields -s. e in [40,50): sx=-5 singles; [50,59): sy=-5 singles.
// Pair (1,0) at e=0 and (0,1) at e=8 -> V accumulates in reference order.
__device__ __forceinline__ void decode_event(int e, int& sx, int& sy,
                                             bool& pair) {
  if (e < 4)       { sx = e + 1;               sy = 0;            pair = true; }
  else if (e < 40) { int t = e - 4; sy = 1 + t / 9; sx = t % 9 - 4;
                     pair = true; }
  else if (e < 50) { sx = -5;                  sy = (e - 40) - 5; pair = false; }
  else             { sy = -5;                  sx = (e - 50) - 4; pair = false; }
}

// Fused diffsq + horizontal 7-tap conv (f32x2), fp16x2 store.
__device__ __forceinline__ void produce_unit(const u64* __restrict__ sImg,
                                             u32* __restrict__ Bdst,
                                             int r1, int j1, int sx, int sy,
                                             u64 gx0, u64 gx1, u64 gx2) {
  const u64* pa = sImg + (r1 + 4) * IP + (j1 + 4);
  const u64* pb = sImg + (r1 + 4 - sy) * IP + (j1 + 4 - sx);
  u64 dsq[18];
#pragma unroll
  for (int k = 0; k < 18; k++) {
    u64 d = f2sub(pa[k], pb[k]);
    dsq[k] = f2mul(d, d);
  }
  u32* pr = Bdst + r1 * BP + j1;
#pragma unroll
  for (int c = 0; c < 12; c++) {
    u64 v = f2mul(gx0, dsq[c]);
    v = f2fma(gx1, dsq[c + 1], v);
    v = f2fma(gx2, dsq[c + 2], v);
    v = f2add(v, dsq[c + 3]);  // center tap weight == 1
    v = f2fma(gx2, dsq[c + 4], v);
    v = f2fma(gx1, dsq[c + 5], v);
    v = f2fma(gx0, dsq[c + 6], v);
    pr[c] = f2h2(v);
  }
}

__device__ __forceinline__ u32 col7h(const u32* rv, int i,
                                     u32 hy0, u32 hy1, u32 hy2, u32 hy3) {
  u32 v = h2mul(hy0, rv[i]);
  v = h2fma(hy1, rv[i + 1], v);
  v = h2fma(hy2, rv[i + 2], v);
  v = h2fma(hy3, rv[i + 3], v);
  v = h2fma(hy2, rv[i + 4], v);
  v = h2fma(hy1, rv[i + 5], v);
  v = h2fma(hy0, rv[i + 6], v);
  return v;
}

extern "C" __global__ void __launch_bounds__(NTHREADS, 2)
mind_main(const float* __restrict__ pred, const float* __restrict__ gt,
          float* __restrict__ out) {
  extern __shared__ u64 smem[];
  u64* sImg = smem;
  u32* bufbase = (u32*)(smem + RH * IP);
  u32* buf[2] = {bufbase, bufbase + BROWS * BP};

  const int tX = blockIdx.x, tY = blockIdx.y, b = blockIdx.z;
  const int tid = threadIdx.x;
  const float* imgP = pred + b * HIMG * WIMG;
  const float* imgG = gt + b * HIMG * WIMG;

  // Load tile + halo (circular wrap). abs row = tY*32 + mr,
  // abs col = tX*64 + mc - 4 (both mod 384).
  float2* sImgF = (float2*)sImg;
  for (int i = tid; i < RH * RW; i += NTHREADS) {
    int mr = i / RW, mc = i - mr * RW;
    int gr = tY * TILE_H + mr; if (gr >= HIMG) gr -= HIMG;
    int gc = tX * TILE_W + mc - 4;
    if (gc < 0) gc += WIMG;
    if (gc >= WIMG) gc -= WIMG;
    sImgF[mr * IP + mc] = make_float2(imgP[gr * WIMG + gc],
                                      imgG[gr * WIMG + gc]);
  }
  __syncthreads();

  // Row-stage: 252 width-12 units = 42 buffer rows x 6 blocks.
  const bool rowAct = tid < 252;
  const int r1 = tid % 42;
  const int j1 = (tid / 42) * 12;

  // Col-stage: 64 cols x 4 groups of 8 rows (all 256 threads).
  const int cc = tid & 63;
  const int gg = tid >> 6;
  const int rbase = gg * 8;
  const int cc4 = cc + 4;           // buffer col of pixel col cc
  const bool cOK = (tX * TILE_W + cc) < INNER;
  const int py0 = tY * TILE_H + rbase;

  const u64 gx0 = bcast2(GX0), gx1 = bcast2(GX1), gx2 = bcast2(GX2);
  const u32 hy0 = bch2(GY0), hy1 = bch2(GY1), hy2 = bch2(GY2),
            hy3 = bch2(GY3);

  u32 Dmin16[8];
  float Vp[8], Vg[8];
#pragma unroll
  for (int i = 0; i < 8; i++) {
    Dmin16[i] = 0x7BFF7BFFu;   // packed fp16 max-finite
    Vp[i] = 0.f; Vg[i] = 0.f;
  }

  int sx, sy; bool isPair;

  // ---------------- Pass A: Dmin and cardinal sum -> invV ----------------
  decode_event(0, sx, sy, isPair);
  if (rowAct) produce_unit(sImg, buf[0], r1, j1, sx, sy, gx0, gx1, gx2);
  __syncthreads();
  for (int e = 0; e < NEVENTS; e++) {
    int cur = e & 1;
    decode_event(e, sx, sy, isPair);
    const u32* bc = buf[cur];
    u32 rv[14];
#pragma unroll
    for (int i = 0; i < 14; i++) rv[i] = bc[(rbase + i) * BP + cc4];
    if (isPair) {
      u32 D1[8];
#pragma unroll
      for (int i = 0; i < 8; i++) D1[i] = col7h(rv, i, hy0, hy1, hy2, hy3);
      const u32* bp2 = bc + sy * BP + sx;
#pragma unroll
      for (int i = 0; i < 14; i++) rv[i] = bp2[(rbase + i) * BP + cc4];
#pragma unroll
      for (int i = 0; i < 8; i++) {
        u32 D2 = col7h(rv, i, hy0, hy1, hy2, hy3);
        Dmin16[i] = h2min(Dmin16[i], h2min(D1[i], D2));
        if (e == 0) {            // pair (1,0): V = D(-1,0) + D(1,0)
          float p1, g1, p2, g2;
          h2up(D1[i], p1, g1); h2up(D2, p2, g2);
          Vp[i] = p2 + p1; Vg[i] = g2 + g1;
        } else if (e == 8) {     // pair (0,1): V = (V + D(0,-1)) + D(0,1)
          float p1, g1, p2, g2;
          h2up(D1[i], p1, g1); h2up(D2, p2, g2);
          Vp[i] = (Vp[i] + p2) + p1; Vg[i] = (Vg[i] + g2) + g1;
        }
      }
    } else {
#pragma unroll
      for (int i = 0; i < 8; i++) {
        u32 D1 = col7h(rv, i, hy0, hy1, hy2, hy3);
        Dmin16[i] = h2min(Dmin16[i], D1);
      }
    }
    if (e + 1 < NEVENTS) {
      int nsx, nsy; bool npair;
      decode_event(e + 1, nsx, nsy, npair);
      if (rowAct && (npair || r1 < 38))
        produce_unit(sImg, buf[cur ^ 1], r1, j1, nsx, nsy, gx0, gx1, gx2);
    }
    __syncthreads();
  }
  float invVp[8], invVg[8];
#pragma unroll
  for (int i = 0; i < 8; i++) {
    invVp[i] = 1.0f / (Vp[i] * 0.25f + 1e-5f);
    invVg[i] = 1.0f / (Vg[i] * 0.25f + 1e-5f);
  }

  // ---------------- Pass B: accumulate |Mp - Mg| ----------------
  float acc = 0.f;
  decode_event(0, sx, sy, isPair);
  if (rowAct) produce_unit(sImg, buf[0], r1, j1, sx, sy, gx0, gx1, gx2);
  __syncthreads();
  for (int e = 0; e < NEVENTS; e++) {
    int cur = e & 1;
    decode_event(e, sx, sy, isPair);
    const u32* bc = buf[cur];
    u32 rv[14];
#pragma unroll
    for (int i = 0; i < 14; i++) rv[i] = bc[(rbase + i) * BP + cc4];
    float lacc = 0.f;
    if (isPair) {
      u32 D1[8];
#pragma unroll
      for (int i = 0; i < 8; i++) D1[i] = col7h(rv, i, hy0, hy1, hy2, hy3);
      const u32* bp2 = bc + sy * BP + sx;
#pragma unroll
      for (int i = 0; i < 14; i++) rv[i] = bp2[(rbase + i) * BP + cc4];
#pragma unroll
      for (int i = 0; i < 8; i++) {
        u32 D2 = col7h(rv, i, hy0, hy1, hy2, hy3);
        u32 t1 = h2sub(Dmin16[i], D1[i]);   // <= 0 by construction
        u32 t2 = h2sub(Dmin16[i], D2);
        float a1, b1, a2, b2;
        h2up(t1, a1, b1); h2up(t2, a2, b2);
        float t = fabsf(__expf(a1 * invVp[i]) - __expf(b1 * invVg[i])) +
                  fabsf(__expf(a2 * invVp[i]) - __expf(b2 * invVg[i]));
        if ((py0 + i) < INNER) lacc += t;
      }
    } else {
#pragma unroll
      for (int i = 0; i < 8; i++) {
        u32 D1 = col7h(rv, i, hy0, hy1, hy2, hy3);
        u32 t1 = h2sub(Dmin16[i], D1);
        float a1, b1; h2up(t1, a1, b1);
        float t = fabsf(__expf(a1 * invVp[i]) - __expf(b1 * invVg[i]));
        if ((py0 + i) < INNER) lacc += t;
      }
    }
    if (cOK) acc += lacc;
    if (e + 1 < NEVENTS) {
      int nsx, nsy; bool npair;
      decode_event(e + 1, nsx, nsy, npair);
      if (rowAct && (npair || r1 < 38))
        produce_unit(sImg, buf[cur ^ 1], r1, j1, nsx, nsy, gx0, gx1, gx2);
    }
    __syncthreads();
  }

  // ---------------- Per-CTA reduction (deterministic) ----------------
#pragma unroll
  for (int o = 16; o > 0; o >>= 1) acc += __shfl_down_sync(0xffffffffu, acc, o);
  float* red = (float*)smem;   // passes done; safe reuse
  if ((tid & 31) == 0) red[tid >> 5] = acc;
  __syncthreads();
  const int ctaIdx = (b * TILES_Y + tY) * TILES_X + tX;
  if (tid == 0) {
    float s = 0.f;
#pragma unroll
    for (int ww = 0; ww < NTHREADS / 32; ww++) s += red[ww];
    g_partials[ctaIdx] = s;
    __threadfence();
    unsigned int old = atomicAdd(&g_count, 1u);
    red[8] = (old == NCTAS - 1) ? 1.f : 0.f;
  }
  __syncthreads();

  // ---------------- Last CTA: global reduction ----------------
  if (red[8] != 0.f) {
    __threadfence();
    float s = g_partials[tid];
    if (tid < NCTAS - NTHREADS) s += g_partials[tid + NTHREADS];
#pragma unroll
    for (int o = 16; o > 0; o >>= 1) s += __shfl_down_sync(0xffffffffu, s, o);
    __syncthreads();
    if ((tid & 31) == 0) red[tid >> 5] = s;
    __syncthreads();
    if (tid == 0) {
      float t = 0.f;
#pragma unroll
      for (int ww = 0; ww < NTHREADS / 32; ww++) t += red[ww];
      out[0] = t * (float)(1.0 / ((double)BATCH * INNER * INNER * 99.0));
      g_count = 0;   // reset for next graph replay
    }
  }
}

extern "C" void kernel_launch(void* const* d_in, const int* in_sizes, int n_in,
                              void* d_out, int out_size) {
  const float* pred = (const float*)d_in[0];
  const float* gt = (const float*)d_in[1];
  cudaFuncSetAttribute(mind_main, cudaFuncAttributeMaxDynamicSharedMemorySize,
                       SMEM_BYTES);
  dim3 grid(TILES_X, TILES_Y, BATCH);
  mind_main<<<grid, NTHREADS, SMEM_BYTES>>>(pred, gt, (float*)d_out);
}

// round 10
// speedup vs baseline: 1.2873x; 1.2873x over previous
#include <cuda_runtime.h>

// ---------------------------------------------------------------------------
// MIND loss, fused, single kernel. R10: D-field store/replay.
//   Pass A (59 +/- pair events, barriers): row conv (f32x2) -> fp16x2 buffer,
//   col conv (f16x2) -> D; tracks Dmin/V AND stores every D (fp16x2 packed
//   P,G) to a __device__ scratch array, one slot per shift (99 slots).
//   Pass B (NO barriers, no recompute): each thread streams back exactly the
//   99x8 D values it wrote (same addresses -> program order, no fences) and
//   accumulates |Mp - Mg| via ex2.approx. The entire pass-B row/col conv
//   recompute of R8/R9 is deleted.
// ---------------------------------------------------------------------------

typedef unsigned long long u64;
typedef unsigned int u32;

namespace {
constexpr int HIMG = 384;
constexpr int WIMG = 384;
constexpr int BATCH = 4;
constexpr int INNER = 370;          // 384 - 2*7
constexpr int TILE_H = 32;
constexpr int TILE_W = 64;
constexpr int RH = 47;              // img tile rows (q_r in [-7, 39])
constexpr int RW = 86;              // img tile cols (q_c in [-11, 74])
constexpr int IP = 87;              // img pitch in u64 (odd)
constexpr int BROWS = 42;           // buffer rows (q_r in [-3, 38])
constexpr int BP = 73;              // buffer pitch in b32 (odd)
constexpr int NTHREADS = 256;
constexpr int TILES_X = 6;
constexpr int TILES_Y = 12;
constexpr int NCTAS = BATCH * TILES_X * TILES_Y;   // 288 -> one wave @ occ 2
constexpr int SMEM_BYTES = RH * IP * 8 + 2 * BROWS * BP * 4;  // 57240 B
constexpr int NEVENTS = 59;         // 40 pairs + 19 singles
constexpr int NSLOTS = 99;          // stored D slots per pixel
constexpr int SLOT_U32 = TILE_H * TILE_W;          // 2048 per slot per CTA
constexpr size_t CTA_U32 = (size_t)NSLOTS * SLOT_U32;

constexpr double E98 = 0.32465246735834974;   // exp(-9/8)
constexpr double E48 = 0.60653065971263342;   // exp(-4/8)
constexpr double E18 = 0.88249690258459546;   // exp(-1/8)
constexpr double TPS = 25.132741228718345;    // 8*pi
constexpr float GX0 = (float)E98;
constexpr float GX1 = (float)E48;
constexpr float GX2 = (float)E18;             // center tap == 1
constexpr float GY0 = (float)(E98 / TPS);
constexpr float GY1 = (float)(E48 / TPS);
constexpr float GY2 = (float)(E18 / TPS);
constexpr float GY3 = (float)(1.0 / TPS);
constexpr float LOG2E = 1.4426950408889634f;
}  // namespace

__device__ u32 g_D[(size_t)NCTAS * CTA_U32];   // 233.6 MB scratch
__device__ float g_partials[NCTAS];
__device__ unsigned int g_count = 0;

// ---- packed f32x2 helpers (sm_100+) ----
__device__ __forceinline__ u64 bcast2(float x) {
  u64 r; asm("mov.b64 %0,{%1,%1};" : "=l"(r) : "f"(x)); return r;
}
__device__ __forceinline__ void up2(u64 v, float& a, float& b) {
  asm("mov.b64 {%0,%1},%2;" : "=f"(a), "=f"(b) : "l"(v));
}
__device__ __forceinline__ u64 f2sub(u64 a, u64 b) {
  u64 r; asm("sub.rn.f32x2 %0,%1,%2;" : "=l"(r) : "l"(a), "l"(b)); return r;
}
__device__ __forceinline__ u64 f2mul(u64 a, u64 b) {
  u64 r; asm("mul.rn.f32x2 %0,%1,%2;" : "=l"(r) : "l"(a), "l"(b)); return r;
}
__device__ __forceinline__ u64 f2add(u64 a, u64 b) {
  u64 r; asm("add.rn.f32x2 %0,%1,%2;" : "=l"(r) : "l"(a), "l"(b)); return r;
}
__device__ __forceinline__ u64 f2fma(u64 a, u64 b, u64 c) {
  u64 r; asm("fma.rn.f32x2 %0,%1,%2,%3;" : "=l"(r) : "l"(a), "l"(b), "l"(c));
  return r;
}

// ---- packed f16x2 helpers ----
__device__ __forceinline__ u32 bch2(float x) {
  u32 r; asm("cvt.rn.f16x2.f32 %0,%1,%1;" : "=r"(r) : "f"(x)); return r;
}
__device__ __forceinline__ u32 f2h2(u64 v) {     // f32x2 -> f16x2 (lo=P)
  float a, b; up2(v, a, b);
  u32 r; asm("cvt.rn.f16x2.f32 %0,%1,%2;" : "=r"(r) : "f"(b), "f"(a));
  return r;
}
__device__ __forceinline__ void h2up(u32 v, float& a, float& b) {
  asm("{\n\t.reg .b16 l,h;\n\tmov.b32 {l,h},%2;\n\t"
      "cvt.f32.f16 %0,l;\n\tcvt.f32.f16 %1,h;\n\t}"
      : "=f"(a), "=f"(b) : "r"(v));
}
__device__ __forceinline__ u32 h2mul(u32 a, u32 b) {
  u32 r; asm("mul.rn.f16x2 %0,%1,%2;" : "=r"(r) : "r"(a), "r"(b)); return r;
}
__device__ __forceinline__ u32 h2fma(u32 a, u32 b, u32 c) {
  u32 r; asm("fma.rn.f16x2 %0,%1,%2,%3;" : "=r"(r) : "r"(a), "r"(b), "r"(c));
  return r;
}
__device__ __forceinline__ u32 h2min(u32 a, u32 b) {
  u32 r; asm("min.f16x2 %0,%1,%2;" : "=r"(r) : "r"(a), "r"(b)); return r;
}
__device__ __forceinline__ u32 h2sub(u32 a, u32 b) {
  u32 r; asm("sub.rn.f16x2 %0,%1,%2;" : "=r"(r) : "r"(a), "r"(b)); return r;
}
__device__ __forceinline__ float ex2(float x) {
  float r; asm("ex2.approx.f32 %0,%1;" : "=f"(r) : "f"(x)); return r;
}

// Event schedule. e<40: pair representatives (sy>0, or sy==0 && sx>=1);
// each also yields -s. e in [40,50): sx=-5 singles; [50,59): sy=-5 singles.
// Pair (1,0) at e=0 and (0,1) at e=8 -> V accumulates in reference order.
__device__ __forceinline__ void decode_event(int e, int& sx, int& sy,
                                             bool& pair) {
  if (e < 4)       { sx = e + 1;               sy = 0;            pair = true; }
  else if (e < 40) { int t = e - 4; sy = 1 + t / 9; sx = t % 9 - 4;
                     pair = true; }
  else if (e < 50) { sx = -5;                  sy = (e - 40) - 5; pair = false; }
  else             { sy = -5;                  sx = (e - 50) - 4; pair = false; }
}

// Fused diffsq + horizontal 7-tap conv (f32x2), fp16x2 store.
__device__ __forceinline__ void produce_unit(const u64* __restrict__ sImg,
                                             u32* __restrict__ Bdst,
                                             int r1, int j1, int sx, int sy,
                                             u64 gx0, u64 gx1, u64 gx2) {
  const u64* pa = sImg + (r1 + 4) * IP + (j1 + 4);
  const u64* pb = sImg + (r1 + 4 - sy) * IP + (j1 + 4 - sx);
  u64 dsq[18];
#pragma unroll
  for (int k = 0; k < 18; k++) {
    u64 d = f2sub(pa[k], pb[k]);
    dsq[k] = f2mul(d, d);
  }
  u32* pr = Bdst + r1 * BP + j1;
#pragma unroll
  for (int c = 0; c < 12; c++) {
    u64 v = f2mul(gx0, dsq[c]);
    v = f2fma(gx1, dsq[c + 1], v);
    v = f2fma(gx2, dsq[c + 2], v);
    v = f2add(v, dsq[c + 3]);  // center tap weight == 1
    v = f2fma(gx2, dsq[c + 4], v);
    v = f2fma(gx1, dsq[c + 5], v);
    v = f2fma(gx0, dsq[c + 6], v);
    pr[c] = f2h2(v);
  }
}

__device__ __forceinline__ u32 col7h(const u32* rv, int i,
                                     u32 hy0, u32 hy1, u32 hy2, u32 hy3) {
  u32 v = h2mul(hy0, rv[i]);
  v = h2fma(hy1, rv[i + 1], v);
  v = h2fma(hy2, rv[i + 2], v);
  v = h2fma(hy3, rv[i + 3], v);
  v = h2fma(hy2, rv[i + 4], v);
  v = h2fma(hy1, rv[i + 5], v);
  v = h2fma(hy0, rv[i + 6], v);
  return v;
}

// Store 8 D values (fp16x2 each) for one slot; layout is warp-contiguous:
// slot*2048 + half*1024 + tid*4 + (i&3) -> perfect 128B coalescing.
__device__ __forceinline__ void store_slot(u32* __restrict__ dst,
                                           const u32 D[8]) {
  ((uint4*)dst)[0] = make_uint4(D[0], D[1], D[2], D[3]);
  ((uint4*)(dst + 1024))[0] = make_uint4(D[4], D[5], D[6], D[7]);
}

extern "C" __global__ void __launch_bounds__(NTHREADS, 2)
mind_main(const float* __restrict__ pred, const float* __restrict__ gt,
          float* __restrict__ out) {
  extern __shared__ u64 smem[];
  u64* sImg = smem;
  u32* bufbase = (u32*)(smem + RH * IP);
  u32* buf[2] = {bufbase, bufbase + BROWS * BP};

  const int tX = blockIdx.x, tY = blockIdx.y, b = blockIdx.z;
  const int tid = threadIdx.x;
  const int ctaIdx = (b * TILES_Y + tY) * TILES_X + tX;
  u32* myD = g_D + (size_t)ctaIdx * CTA_U32 + tid * 4;
  const float* imgP = pred + b * HIMG * WIMG;
  const float* imgG = gt + b * HIMG * WIMG;

  // Load tile + halo (circular wrap). abs row = tY*32 + mr,
  // abs col = tX*64 + mc - 4 (both mod 384).
  float2* sImgF = (float2*)sImg;
  for (int i = tid; i < RH * RW; i += NTHREADS) {
    int mr = i / RW, mc = i - mr * RW;
    int gr = tY * TILE_H + mr; if (gr >= HIMG) gr -= HIMG;
    int gc = tX * TILE_W + mc - 4;
    if (gc < 0) gc += WIMG;
    if (gc >= WIMG) gc -= WIMG;
    sImgF[mr * IP + mc] = make_float2(imgP[gr * WIMG + gc],
                                      imgG[gr * WIMG + gc]);
  }
  __syncthreads();

  // Row-stage: 252 width-12 units = 42 buffer rows x 6 blocks.
  const bool rowAct = tid < 252;
  const int r1 = tid % 42;
  const int j1 = (tid / 42) * 12;

  // Col-stage: 64 cols x 4 groups of 8 rows (all 256 threads).
  const int cc = tid & 63;
  const int gg = tid >> 6;
  const int rbase = gg * 8;
  const int cc4 = cc + 4;           // buffer col of pixel col cc
  const bool cOK = (tX * TILE_W + cc) < INNER;
  const int py0 = tY * TILE_H + rbase;

  const u64 gx0 = bcast2(GX0), gx1 = bcast2(GX1), gx2 = bcast2(GX2);
  const u32 hy0 = bch2(GY0), hy1 = bch2(GY1), hy2 = bch2(GY2),
            hy3 = bch2(GY3);

  u32 Dmin16[8];
  float Vp[8], Vg[8];
#pragma unroll
  for (int i = 0; i < 8; i++) {
    Dmin16[i] = 0x7BFF7BFFu;   // packed fp16 max-finite
    Vp[i] = 0.f; Vg[i] = 0.f;
  }

  int sx, sy; bool isPair;

  // -------- Pass A: D fields -> gmem slots; Dmin + cardinal V --------
  decode_event(0, sx, sy, isPair);
  if (rowAct) produce_unit(sImg, buf[0], r1, j1, sx, sy, gx0, gx1, gx2);
  __syncthreads();
  for (int e = 0; e < NEVENTS; e++) {
    int cur = e & 1;
    decode_event(e, sx, sy, isPair);
    const u32* bc = buf[cur];
    u32 rv[14];
#pragma unroll
    for (int i = 0; i < 14; i++) rv[i] = bc[(rbase + i) * BP + cc4];
    u32 D1[8];
#pragma unroll
    for (int i = 0; i < 8; i++) D1[i] = col7h(rv, i, hy0, hy1, hy2, hy3);
    store_slot(myD + e * SLOT_U32, D1);
    if (isPair) {
      const u32* bp2 = bc + sy * BP + sx;
#pragma unroll
      for (int i = 0; i < 14; i++) rv[i] = bp2[(rbase + i) * BP + cc4];
      u32 D2[8];
#pragma unroll
      for (int i = 0; i < 8; i++) D2[i] = col7h(rv, i, hy0, hy1, hy2, hy3);
      store_slot(myD + (NEVENTS + e) * SLOT_U32, D2);
#pragma unroll
      for (int i = 0; i < 8; i++) {
        Dmin16[i] = h2min(Dmin16[i], h2min(D1[i], D2[i]));
        if (e == 0) {            // pair (1,0): V = D(-1,0) + D(1,0)
          float p1, g1, p2, g2;
          h2up(D1[i], p1, g1); h2up(D2[i], p2, g2);
          Vp[i] = p2 + p1; Vg[i] = g2 + g1;
        } else if (e == 8) {     // pair (0,1): V = (V + D(0,-1)) + D(0,1)
          float p1, g1, p2, g2;
          h2up(D1[i], p1, g1); h2up(D2[i], p2, g2);
          Vp[i] = (Vp[i] + p2) + p1; Vg[i] = (Vg[i] + g2) + g1;
        }
      }
    } else {
#pragma unroll
      for (int i = 0; i < 8; i++) Dmin16[i] = h2min(Dmin16[i], D1[i]);
    }
    if (e + 1 < NEVENTS) {
      int nsx, nsy; bool npair;
      decode_event(e + 1, nsx, nsy, npair);
      if (rowAct && (npair || r1 < 38))
        produce_unit(sImg, buf[cur ^ 1], r1, j1, nsx, nsy, gx0, gx1, gx2);
    }
    __syncthreads();
  }
  float invVpL2[8], invVgL2[8];
#pragma unroll
  for (int i = 0; i < 8; i++) {
    invVpL2[i] = LOG2E / (Vp[i] * 0.25f + 1e-5f);
    invVgL2[i] = LOG2E / (Vg[i] * 0.25f + 1e-5f);
  }

  // -------- Pass B: stream D back (same thread, same addresses; no
  // barriers, no fences needed) and accumulate |Mp - Mg| --------
  float acc = 0.f;
#pragma unroll 3
  for (int slot = 0; slot < NSLOTS; slot++) {
    uint4 lo = ((const uint4*)(myD + slot * SLOT_U32))[0];
    uint4 hi = ((const uint4*)(myD + slot * SLOT_U32 + 1024))[0];
    u32 Ds[8] = {lo.x, lo.y, lo.z, lo.w, hi.x, hi.y, hi.z, hi.w};
#pragma unroll
    for (int i = 0; i < 8; i++) {
      u32 t = h2sub(Dmin16[i], Ds[i]);   // <= 0 by construction
      float a1, b1; h2up(t, a1, b1);
      float term = fabsf(ex2(a1 * invVpL2[i]) - ex2(b1 * invVgL2[i]));
      if (cOK && (py0 + i) < INNER) acc += term;
    }
  }

  // ---------------- Per-CTA reduction (deterministic) ----------------
#pragma unroll
  for (int o = 16; o > 0; o >>= 1) acc += __shfl_down_sync(0xffffffffu, acc, o);
  __syncthreads();             // all pass-A smem use done
  float* red = (float*)smem;
  if ((tid & 31) == 0) red[tid >> 5] = acc;
  __syncthreads();
  if (tid == 0) {
    float s = 0.f;
#pragma unroll
    for (int ww = 0; ww < NTHREADS / 32; ww++) s += red[ww];
    g_partials[ctaIdx] = s;
    __threadfence();
    unsigned int old = atomicAdd(&g_count, 1u);
    red[8] = (old == NCTAS - 1) ? 1.f : 0.f;
  }
  __syncthreads();

  // ---------------- Last CTA: global reduction ----------------
  if (red[8] != 0.f) {
    __threadfence();
    float s = g_partials[tid];
    if (tid < NCTAS - NTHREADS) s += g_partials[tid + NTHREADS];
#pragma unroll
    for (int o = 16; o > 0; o >>= 1) s += __shfl_down_sync(0xffffffffu, s, o);
    __syncthreads();
    if ((tid & 31) == 0) red[tid >> 5] = s;
    __syncthreads();
    if (tid == 0) {
      float t = 0.f;
#pragma unroll
      for (int ww = 0; ww < NTHREADS / 32; ww++) t += red[ww];
      out[0] = t * (float)(1.0 / ((double)BATCH * INNER * INNER * 99.0));
      g_count = 0;   // reset for next graph replay
    }
  }
}

extern "C" void kernel_launch(void* const* d_in, const int* in_sizes, int n_in,
                              void* d_out, int out_size) {
  const float* pred = (const float*)d_in[0];
  const float* gt = (const float*)d_in[1];
  cudaFuncSetAttribute(mind_main, cudaFuncAttributeMaxDynamicSharedMemorySize,
                       SMEM_BYTES);
  dim3 grid(TILES_X, TILES_Y, BATCH);
  mind_main<<<grid, NTHREADS, SMEM_BYTES>>>(pred, gt, (float*)d_out);
}

// round 11
// speedup vs baseline: 1.5322x; 1.1902x over previous
#include <cuda_runtime.h>

// ---------------------------------------------------------------------------
// MIND loss, fused, single kernel. R11 = R10 (D-field store/replay) +
//  - quad-buffered pass A: produce/consume TWO events per __syncthreads
//    (30 barriers instead of 59)
//  - pass B reads slots in REVERSE write order -> recent writes hit L2
//  - branchless masked accumulation in pass B
// Pass A: row conv (f32x2) -> fp16x2 smem buffer, col conv (f16x2) -> D;
//   tracks Dmin (min.f16x2) + cardinal V, stores every D (fp16x2 P,G) to a
//   __device__ scratch array (99 slots/px). Pass B: barrier-free streaming
//   epilogue over the thread's own slots (same addresses -> program order).
// ---------------------------------------------------------------------------

typedef unsigned long long u64;
typedef unsigned int u32;

namespace {
constexpr int HIMG = 384;
constexpr int WIMG = 384;
constexpr int BATCH = 4;
constexpr int INNER = 370;          // 384 - 2*7
constexpr int TILE_H = 32;
constexpr int TILE_W = 64;
constexpr int RH = 47;              // img tile rows (q_r in [-7, 39])
constexpr int RW = 86;              // img tile cols (q_c in [-11, 74])
constexpr int IP = 87;              // img pitch in u64 (odd)
constexpr int BROWS = 42;           // buffer rows (q_r in [-3, 38])
constexpr int BP = 73;              // buffer pitch in b32 (odd)
constexpr int NTHREADS = 256;
constexpr int TILES_X = 6;
constexpr int TILES_Y = 12;
constexpr int NCTAS = BATCH * TILES_X * TILES_Y;   // 288 -> one wave @ occ 2
constexpr int SMEM_BYTES = RH * IP * 8 + 4 * BROWS * BP * 4;  // 81768 B
constexpr int NEVENTS = 59;         // 40 pairs + 19 singles
constexpr int NSLOTS = 99;          // stored D slots per pixel
constexpr int SLOT_U32 = TILE_H * TILE_W;          // 2048 per slot per CTA
constexpr size_t CTA_U32 = (size_t)NSLOTS * SLOT_U32;

constexpr double E98 = 0.32465246735834974;   // exp(-9/8)
constexpr double E48 = 0.60653065971263342;   // exp(-4/8)
constexpr double E18 = 0.88249690258459546;   // exp(-1/8)
constexpr double TPS = 25.132741228718345;    // 8*pi
constexpr float GX0 = (float)E98;
constexpr float GX1 = (float)E48;
constexpr float GX2 = (float)E18;             // center tap == 1
constexpr float GY0 = (float)(E98 / TPS);
constexpr float GY1 = (float)(E48 / TPS);
constexpr float GY2 = (float)(E18 / TPS);
constexpr float GY3 = (float)(1.0 / TPS);
constexpr float LOG2E = 1.4426950408889634f;
}  // namespace

__device__ u32 g_D[(size_t)NCTAS * CTA_U32];   // 233.6 MB scratch
__device__ float g_partials[NCTAS];
__device__ unsigned int g_count = 0;

// ---- packed f32x2 helpers (sm_100+) ----
__device__ __forceinline__ u64 bcast2(float x) {
  u64 r; asm("mov.b64 %0,{%1,%1};" : "=l"(r) : "f"(x)); return r;
}
__device__ __forceinline__ void up2(u64 v, float& a, float& b) {
  asm("mov.b64 {%0,%1},%2;" : "=f"(a), "=f"(b) : "l"(v));
}
__device__ __forceinline__ u64 f2sub(u64 a, u64 b) {
  u64 r; asm("sub.rn.f32x2 %0,%1,%2;" : "=l"(r) : "l"(a), "l"(b)); return r;
}
__device__ __forceinline__ u64 f2mul(u64 a, u64 b) {
  u64 r; asm("mul.rn.f32x2 %0,%1,%2;" : "=l"(r) : "l"(a), "l"(b)); return r;
}
__device__ __forceinline__ u64 f2add(u64 a, u64 b) {
  u64 r; asm("add.rn.f32x2 %0,%1,%2;" : "=l"(r) : "l"(a), "l"(b)); return r;
}
__device__ __forceinline__ u64 f2fma(u64 a, u64 b, u64 c) {
  u64 r; asm("fma.rn.f32x2 %0,%1,%2,%3;" : "=l"(r) : "l"(a), "l"(b), "l"(c));
  return r;
}

// ---- packed f16x2 helpers ----
__device__ __forceinline__ u32 bch2(float x) {
  u32 r; asm("cvt.rn.f16x2.f32 %0,%1,%1;" : "=r"(r) : "f"(x)); return r;
}
__device__ __forceinline__ u32 f2h2(u64 v) {     // f32x2 -> f16x2 (lo=P)
  float a, b; up2(v, a, b);
  u32 r; asm("cvt.rn.f16x2.f32 %0,%1,%2;" : "=r"(r) : "f"(b), "f"(a));
  return r;
}
__device__ __forceinline__ void h2up(u32 v, float& a, float& b) {
  asm("{\n\t.reg .b16 l,h;\n\tmov.b32 {l,h},%2;\n\t"
      "cvt.f32.f16 %0,l;\n\tcvt.f32.f16 %1,h;\n\t}"
      : "=f"(a), "=f"(b) : "r"(v));
}
__device__ __forceinline__ u32 h2mul(u32 a, u32 b) {
  u32 r; asm("mul.rn.f16x2 %0,%1,%2;" : "=r"(r) : "r"(a), "r"(b)); return r;
}
__device__ __forceinline__ u32 h2fma(u32 a, u32 b, u32 c) {
  u32 r; asm("fma.rn.f16x2 %0,%1,%2,%3;" : "=r"(r) : "r"(a), "r"(b), "r"(c));
  return r;
}
__device__ __forceinline__ u32 h2min(u32 a, u32 b) {
  u32 r; asm("min.f16x2 %0,%1,%2;" : "=r"(r) : "r"(a), "r"(b)); return r;
}
__device__ __forceinline__ u32 h2sub(u32 a, u32 b) {
  u32 r; asm("sub.rn.f16x2 %0,%1,%2;" : "=r"(r) : "r"(a), "r"(b)); return r;
}
__device__ __forceinline__ float ex2(float x) {
  float r; asm("ex2.approx.f32 %0,%1;" : "=f"(r) : "f"(x)); return r;
}

// Event schedule. e<40: pair representatives (sy>0, or sy==0 && sx>=1);
// each also yields -s. e in [40,50): sx=-5 singles; [50,59): sy=-5 singles.
// Pair (1,0) at e=0 and (0,1) at e=8 -> V accumulates in reference order.
__device__ __forceinline__ void decode_event(int e, int& sx, int& sy,
                                             bool& pair) {
  if (e < 4)       { sx = e + 1;               sy = 0;            pair = true; }
  else if (e < 40) { int t = e - 4; sy = 1 + t / 9; sx = t % 9 - 4;
                     pair = true; }
  else if (e < 50) { sx = -5;                  sy = (e - 40) - 5; pair = false; }
  else             { sy = -5;                  sx = (e - 50) - 4; pair = false; }
}

// Fused diffsq + horizontal 7-tap conv (f32x2), fp16x2 store.
__device__ __forceinline__ void produce_unit(const u64* __restrict__ sImg,
                                             u32* __restrict__ Bdst,
                                             int r1, int j1, int sx, int sy,
                                             u64 gx0, u64 gx1, u64 gx2) {
  const u64* pa = sImg + (r1 + 4) * IP + (j1 + 4);
  const u64* pb = sImg + (r1 + 4 - sy) * IP + (j1 + 4 - sx);
  u64 dsq[18];
#pragma unroll
  for (int k = 0; k < 18; k++) {
    u64 d = f2sub(pa[k], pb[k]);
    dsq[k] = f2mul(d, d);
  }
  u32* pr = Bdst + r1 * BP + j1;
#pragma unroll
  for (int c = 0; c < 12; c++) {
    u64 v = f2mul(gx0, dsq[c]);
    v = f2fma(gx1, dsq[c + 1], v);
    v = f2fma(gx2, dsq[c + 2], v);
    v = f2add(v, dsq[c + 3]);  // center tap weight == 1
    v = f2fma(gx2, dsq[c + 4], v);
    v = f2fma(gx1, dsq[c + 5], v);
    v = f2fma(gx0, dsq[c + 6], v);
    pr[c] = f2h2(v);
  }
}

__device__ __forceinline__ u32 col7h(const u32* rv, int i,
                                     u32 hy0, u32 hy1, u32 hy2, u32 hy3) {
  u32 v = h2mul(hy0, rv[i]);
  v = h2fma(hy1, rv[i + 1], v);
  v = h2fma(hy2, rv[i + 2], v);
  v = h2fma(hy3, rv[i + 3], v);
  v = h2fma(hy2, rv[i + 4], v);
  v = h2fma(hy1, rv[i + 5], v);
  v = h2fma(hy0, rv[i + 6], v);
  return v;
}

// Store 8 D values (fp16x2 each) for one slot; layout warp-contiguous:
// slot*2048 + half*1024 + tid*4 -> 128B coalescing per warp.
__device__ __forceinline__ void store_slot(u32* __restrict__ dst,
                                           const u32 D[8]) {
  ((uint4*)dst)[0] = make_uint4(D[0], D[1], D[2], D[3]);
  ((uint4*)(dst + 1024))[0] = make_uint4(D[4], D[5], D[6], D[7]);
}

extern "C" __global__ void __launch_bounds__(NTHREADS, 2)
mind_main(const float* __restrict__ pred, const float* __restrict__ gt,
          float* __restrict__ out) {
  extern __shared__ u64 smem[];
  u64* sImg = smem;
  u32* bufbase = (u32*)(smem + RH * IP);
  u32* buf[4] = {bufbase, bufbase + BROWS * BP,
                 bufbase + 2 * BROWS * BP, bufbase + 3 * BROWS * BP};

  const int tX = blockIdx.x, tY = blockIdx.y, b = blockIdx.z;
  const int tid = threadIdx.x;
  const int ctaIdx = (b * TILES_Y + tY) * TILES_X + tX;
  u32* myD = g_D + (size_t)ctaIdx * CTA_U32 + tid * 4;
  const float* imgP = pred + b * HIMG * WIMG;
  const float* imgG = gt + b * HIMG * WIMG;

  // Load tile + halo (circular wrap). abs row = tY*32 + mr,
  // abs col = tX*64 + mc - 4 (both mod 384).
  float2* sImgF = (float2*)sImg;
  for (int i = tid; i < RH * RW; i += NTHREADS) {
    int mr = i / RW, mc = i - mr * RW;
    int gr = tY * TILE_H + mr; if (gr >= HIMG) gr -= HIMG;
    int gc = tX * TILE_W + mc - 4;
    if (gc < 0) gc += WIMG;
    if (gc >= WIMG) gc -= WIMG;
    sImgF[mr * IP + mc] = make_float2(imgP[gr * WIMG + gc],
                                      imgG[gr * WIMG + gc]);
  }
  __syncthreads();

  // Row-stage: 252 width-12 units = 42 buffer rows x 6 blocks.
  const bool rowAct = tid < 252;
  const int r1 = tid % 42;
  const int j1 = (tid / 42) * 12;

  // Col-stage: 64 cols x 4 groups of 8 rows (all 256 threads).
  const int cc = tid & 63;
  const int gg = tid >> 6;
  const int rbase = gg * 8;
  const int cc4 = cc + 4;           // buffer col of pixel col cc
  const bool cOK = (tX * TILE_W + cc) < INNER;
  const int py0 = tY * TILE_H + rbase;

  const u64 gx0 = bcast2(GX0), gx1 = bcast2(GX1), gx2 = bcast2(GX2);
  const u32 hy0 = bch2(GY0), hy1 = bch2(GY1), hy2 = bch2(GY2),
            hy3 = bch2(GY3);

  u32 Dmin16[8];
  float Vp[8], Vg[8];
#pragma unroll
  for (int i = 0; i < 8; i++) {
    Dmin16[i] = 0x7BFF7BFFu;   // packed fp16 max-finite
    Vp[i] = 0.f; Vg[i] = 0.f;
  }

  // -------- Pass A: D fields -> gmem slots; Dmin + cardinal V --------
  // Quad-buffered: iteration k consumes events {2k, 2k+1} from buffer set
  // (k&1), produces events {2k+2, 2k+3} into the other set. One barrier
  // per iteration (30 total).
  {
    int sx, sy; bool isPair;
    decode_event(0, sx, sy, isPair);
    if (rowAct) produce_unit(sImg, buf[0], r1, j1, sx, sy, gx0, gx1, gx2);
    decode_event(1, sx, sy, isPair);
    if (rowAct) produce_unit(sImg, buf[1], r1, j1, sx, sy, gx0, gx1, gx2);
  }
  __syncthreads();

  for (int k = 0; k < 30; k++) {
    const int setc = (k & 1) << 1;       // consume buffers setc, setc+1
    // ---- consume events 2k, 2k+1 ----
#pragma unroll
    for (int ee = 0; ee < 2; ee++) {
      const int e = 2 * k + ee;
      if (e >= NEVENTS) break;
      int sx, sy; bool isPair;
      decode_event(e, sx, sy, isPair);
      const u32* bc = buf[setc + ee];
      u32 rv[14];
#pragma unroll
      for (int i = 0; i < 14; i++) rv[i] = bc[(rbase + i) * BP + cc4];
      u32 D1[8];
#pragma unroll
      for (int i = 0; i < 8; i++) D1[i] = col7h(rv, i, hy0, hy1, hy2, hy3);
      store_slot(myD + e * SLOT_U32, D1);
      if (isPair) {
        const u32* bp2 = bc + sy * BP + sx;
#pragma unroll
        for (int i = 0; i < 14; i++) rv[i] = bp2[(rbase + i) * BP + cc4];
        u32 D2[8];
#pragma unroll
        for (int i = 0; i < 8; i++) D2[i] = col7h(rv, i, hy0, hy1, hy2, hy3);
        store_slot(myD + (NEVENTS + e) * SLOT_U32, D2);
#pragma unroll
        for (int i = 0; i < 8; i++) {
          Dmin16[i] = h2min(Dmin16[i], h2min(D1[i], D2[i]));
          if (e == 0) {            // pair (1,0): V = D(-1,0) + D(1,0)
            float p1, g1, p2, g2;
            h2up(D1[i], p1, g1); h2up(D2[i], p2, g2);
            Vp[i] = p2 + p1; Vg[i] = g2 + g1;
          } else if (e == 8) {     // pair (0,1): V = (V + D(0,-1)) + D(0,1)
            float p1, g1, p2, g2;
            h2up(D1[i], p1, g1); h2up(D2[i], p2, g2);
            Vp[i] = (Vp[i] + p2) + p1; Vg[i] = (Vg[i] + g2) + g1;
          }
        }
      } else {
#pragma unroll
        for (int i = 0; i < 8; i++) Dmin16[i] = h2min(Dmin16[i], D1[i]);
      }
    }
    // ---- produce events 2k+2, 2k+3 into the other set ----
    const int setp = ((k + 1) & 1) << 1;
#pragma unroll
    for (int ee = 0; ee < 2; ee++) {
      const int e = 2 * k + 2 + ee;
      if (e >= NEVENTS) break;
      int sx, sy; bool isPair;
      decode_event(e, sx, sy, isPair);
      if (rowAct && (isPair || r1 < 38))
        produce_unit(sImg, buf[setp + ee], r1, j1, sx, sy, gx0, gx1, gx2);
    }
    __syncthreads();
  }

  float invVpL2[8], invVgL2[8], mask[8];
#pragma unroll
  for (int i = 0; i < 8; i++) {
    invVpL2[i] = LOG2E / (Vp[i] * 0.25f + 1e-5f);
    invVgL2[i] = LOG2E / (Vg[i] * 0.25f + 1e-5f);
    mask[i] = (cOK && (py0 + i) < INNER) ? 1.f : 0.f;
  }

  // -------- Pass B: stream D back in REVERSE write order (recent slots
  // still L2-resident). Same thread, same addresses -> program order,
  // no fences, no barriers. --------
  float acc = 0.f;
#pragma unroll 4
  for (int s = 0; s < NSLOTS; s++) {
    const u32* p = myD + (size_t)(NSLOTS - 1 - s) * SLOT_U32;
    uint4 lo = ((const uint4*)p)[0];
    uint4 hi = ((const uint4*)(p + 1024))[0];
    u32 Ds[8] = {lo.x, lo.y, lo.z, lo.w, hi.x, hi.y, hi.z, hi.w};
#pragma unroll
    for (int i = 0; i < 8; i++) {
      u32 t = h2sub(Dmin16[i], Ds[i]);   // <= 0 by construction
      float a1, b1; h2up(t, a1, b1);
      float term = fabsf(ex2(a1 * invVpL2[i]) - ex2(b1 * invVgL2[i]));
      acc = fmaf(mask[i], term, acc);
    }
  }

  // ---------------- Per-CTA reduction (deterministic) ----------------
#pragma unroll
  for (int o = 16; o > 0; o >>= 1) acc += __shfl_down_sync(0xffffffffu, acc, o);
  __syncthreads();             // all pass-A smem use done
  float* red = (float*)smem;
  if ((tid & 31) == 0) red[tid >> 5] = acc;
  __syncthreads();
  if (tid == 0) {
    float s = 0.f;
#pragma unroll
    for (int ww = 0; ww < NTHREADS / 32; ww++) s += red[ww];
    g_partials[ctaIdx] = s;
    __threadfence();
    unsigned int old = atomicAdd(&g_count, 1u);
    red[8] = (old == NCTAS - 1) ? 1.f : 0.f;
  }
  __syncthreads();

  // ---------------- Last CTA: global reduction ----------------
  if (red[8] != 0.f) {
    __threadfence();
    float s = g_partials[tid];
    if (tid < NCTAS - NTHREADS) s += g_partials[tid + NTHREADS];
#pragma unroll
    for (int o = 16; o > 0; o >>= 1) s += __shfl_down_sync(0xffffffffu, s, o);
    __syncthreads();
    if ((tid & 31) == 0) red[tid >> 5] = s;
    __syncthreads();
    if (tid == 0) {
      float t = 0.f;
#pragma unroll
      for (int ww = 0; ww < NTHREADS / 32; ww++) t += red[ww];
      out[0] = t * (float)(1.0 / ((double)BATCH * INNER * INNER * 99.0));
      g_count = 0;   // reset for next graph replay
    }
  }
}

extern "C" void kernel_launch(void* const* d_in, const int* in_sizes, int n_in,
                              void* d_out, int out_size) {
  const float* pred = (const float*)d_in[0];
  const float* gt = (const float*)d_in[1];
  cudaFuncSetAttribute(mind_main, cudaFuncAttributeMaxDynamicSharedMemorySize,
                       SMEM_BYTES);
  dim3 grid(TILES_X, TILES_Y, BATCH);
  mind_main<<<grid, NTHREADS, SMEM_BYTES>>>(pred, gt, (float*)d_out);
}

// round 12
// speedup vs baseline: 1.5681x; 1.0234x over previous
#include <cuda_runtime.h>

// ---------------------------------------------------------------------------
// MIND loss, fused, single kernel. R12 = R11 +
//  - pass B exp via ONE ex2.approx.f16x2 per slot-pixel (MUFU halved);
//    args computed in f32 (range-safe), mask folded into invV (=0 -> term 0)
//  - 6 conv buffers, THREE events per __syncthreads (20 barriers vs 30)
// Pass A: row conv (f32x2) -> fp16x2 smem buffer, col conv (f16x2) -> D;
//   Dmin via min.f16x2 + cardinal V in reference fp order; every D stored
//   (fp16x2 P,G) to __device__ scratch (99 slots/px).
// Pass B: barrier-free reverse-order streaming epilogue over own slots.
// ---------------------------------------------------------------------------

typedef unsigned long long u64;
typedef unsigned int u32;

namespace {
constexpr int HIMG = 384;
constexpr int WIMG = 384;
constexpr int BATCH = 4;
constexpr int INNER = 370;          // 384 - 2*7
constexpr int TILE_H = 32;
constexpr int TILE_W = 64;
constexpr int RH = 47;              // img tile rows (q_r in [-7, 39])
constexpr int RW = 86;              // img tile cols (q_c in [-11, 74])
constexpr int IP = 87;              // img pitch in u64 (odd)
constexpr int BROWS = 42;           // buffer rows (q_r in [-3, 38])
constexpr int BP = 73;              // buffer pitch in b32 (odd)
constexpr int NTHREADS = 256;
constexpr int TILES_X = 6;
constexpr int TILES_Y = 12;
constexpr int NCTAS = BATCH * TILES_X * TILES_Y;   // 288 -> one wave @ occ 2
constexpr int NBUF = 6;             // 3 events per barrier, double-banked
constexpr int SMEM_BYTES = RH * IP * 8 + NBUF * BROWS * BP * 4;  // 106296 B
constexpr int NEVENTS = 59;         // 40 pairs + 19 singles
constexpr int NGROUPS = 20;         // ceil(59/3)
constexpr int NSLOTS = 99;          // stored D slots per pixel
constexpr int SLOT_U32 = TILE_H * TILE_W;          // 2048 per slot per CTA
constexpr size_t CTA_U32 = (size_t)NSLOTS * SLOT_U32;

constexpr double E98 = 0.32465246735834974;   // exp(-9/8)
constexpr double E48 = 0.60653065971263342;   // exp(-4/8)
constexpr double E18 = 0.88249690258459546;   // exp(-1/8)
constexpr double TPS = 25.132741228718345;    // 8*pi
constexpr float GX0 = (float)E98;
constexpr float GX1 = (float)E48;
constexpr float GX2 = (float)E18;             // center tap == 1
constexpr float GY0 = (float)(E98 / TPS);
constexpr float GY1 = (float)(E48 / TPS);
constexpr float GY2 = (float)(E18 / TPS);
constexpr float GY3 = (float)(1.0 / TPS);
constexpr float LOG2E = 1.4426950408889634f;
}  // namespace

__device__ u32 g_D[(size_t)NCTAS * CTA_U32];   // 233.6 MB scratch
__device__ float g_partials[NCTAS];
__device__ unsigned int g_count = 0;

// ---- packed f32x2 helpers (sm_100+) ----
__device__ __forceinline__ u64 bcast2(float x) {
  u64 r; asm("mov.b64 %0,{%1,%1};" : "=l"(r) : "f"(x)); return r;
}
__device__ __forceinline__ void up2(u64 v, float& a, float& b) {
  asm("mov.b64 {%0,%1},%2;" : "=f"(a), "=f"(b) : "l"(v));
}
__device__ __forceinline__ u64 f2sub(u64 a, u64 b) {
  u64 r; asm("sub.rn.f32x2 %0,%1,%2;" : "=l"(r) : "l"(a), "l"(b)); return r;
}
__device__ __forceinline__ u64 f2mul(u64 a, u64 b) {
  u64 r; asm("mul.rn.f32x2 %0,%1,%2;" : "=l"(r) : "l"(a), "l"(b)); return r;
}
__device__ __forceinline__ u64 f2add(u64 a, u64 b) {
  u64 r; asm("add.rn.f32x2 %0,%1,%2;" : "=l"(r) : "l"(a), "l"(b)); return r;
}
__device__ __forceinline__ u64 f2fma(u64 a, u64 b, u64 c) {
  u64 r; asm("fma.rn.f32x2 %0,%1,%2,%3;" : "=l"(r) : "l"(a), "l"(b), "l"(c));
  return r;
}

// ---- packed f16x2 helpers ----
__device__ __forceinline__ u32 bch2(float x) {
  u32 r; asm("cvt.rn.f16x2.f32 %0,%1,%1;" : "=r"(r) : "f"(x)); return r;
}
__device__ __forceinline__ u32 f2h2(u64 v) {     // f32x2 -> f16x2 (lo=P)
  float a, b; up2(v, a, b);
  u32 r; asm("cvt.rn.f16x2.f32 %0,%1,%2;" : "=r"(r) : "f"(b), "f"(a));
  return r;
}
__device__ __forceinline__ u32 pkh2(float lo, float hi) {
  u32 r; asm("cvt.rn.f16x2.f32 %0,%1,%2;" : "=r"(r) : "f"(hi), "f"(lo));
  return r;
}
__device__ __forceinline__ void h2up(u32 v, float& a, float& b) {
  asm("{\n\t.reg .b16 l,h;\n\tmov.b32 {l,h},%2;\n\t"
      "cvt.f32.f16 %0,l;\n\tcvt.f32.f16 %1,h;\n\t}"
      : "=f"(a), "=f"(b) : "r"(v));
}
__device__ __forceinline__ u32 h2mul(u32 a, u32 b) {
  u32 r; asm("mul.rn.f16x2 %0,%1,%2;" : "=r"(r) : "r"(a), "r"(b)); return r;
}
__device__ __forceinline__ u32 h2fma(u32 a, u32 b, u32 c) {
  u32 r; asm("fma.rn.f16x2 %0,%1,%2,%3;" : "=r"(r) : "r"(a), "r"(b), "r"(c));
  return r;
}
__device__ __forceinline__ u32 h2min(u32 a, u32 b) {
  u32 r; asm("min.f16x2 %0,%1,%2;" : "=r"(r) : "r"(a), "r"(b)); return r;
}
__device__ __forceinline__ u32 h2sub(u32 a, u32 b) {
  u32 r; asm("sub.rn.f16x2 %0,%1,%2;" : "=r"(r) : "r"(a), "r"(b)); return r;
}
__device__ __forceinline__ u32 ex2h2(u32 x) {    // packed exp2, 1 MUFU op
  u32 r; asm("ex2.approx.f16x2 %0,%1;" : "=r"(r) : "r"(x)); return r;
}

// Event schedule. e<40: pair representatives (sy>0, or sy==0 && sx>=1);
// each also yields -s. e in [40,50): sx=-5 singles; [50,59): sy=-5 singles.
// Pair (1,0) at e=0 and (0,1) at e=8 -> V accumulates in reference order.
__device__ __forceinline__ void decode_event(int e, int& sx, int& sy,
                                             bool& pair) {
  if (e < 4)       { sx = e + 1;               sy = 0;            pair = true; }
  else if (e < 40) { int t = e - 4; sy = 1 + t / 9; sx = t % 9 - 4;
                     pair = true; }
  else if (e < 50) { sx = -5;                  sy = (e - 40) - 5; pair = false; }
  else             { sy = -5;                  sx = (e - 50) - 4; pair = false; }
}

// Fused diffsq + horizontal 7-tap conv (f32x2), fp16x2 store.
__device__ __forceinline__ void produce_unit(const u64* __restrict__ sImg,
                                             u32* __restrict__ Bdst,
                                             int r1, int j1, int sx, int sy,
                                             u64 gx0, u64 gx1, u64 gx2) {
  const u64* pa = sImg + (r1 + 4) * IP + (j1 + 4);
  const u64* pb = sImg + (r1 + 4 - sy) * IP + (j1 + 4 - sx);
  u64 dsq[18];
#pragma unroll
  for (int k = 0; k < 18; k++) {
    u64 d = f2sub(pa[k], pb[k]);
    dsq[k] = f2mul(d, d);
  }
  u32* pr = Bdst + r1 * BP + j1;
#pragma unroll
  for (int c = 0; c < 12; c++) {
    u64 v = f2mul(gx0, dsq[c]);
    v = f2fma(gx1, dsq[c + 1], v);
    v = f2fma(gx2, dsq[c + 2], v);
    v = f2add(v, dsq[c + 3]);  // center tap weight == 1
    v = f2fma(gx2, dsq[c + 4], v);
    v = f2fma(gx1, dsq[c + 5], v);
    v = f2fma(gx0, dsq[c + 6], v);
    pr[c] = f2h2(v);
  }
}

__device__ __forceinline__ u32 col7h(const u32* rv, int i,
                                     u32 hy0, u32 hy1, u32 hy2, u32 hy3) {
  u32 v = h2mul(hy0, rv[i]);
  v = h2fma(hy1, rv[i + 1], v);
  v = h2fma(hy2, rv[i + 2], v);
  v = h2fma(hy3, rv[i + 3], v);
  v = h2fma(hy2, rv[i + 4], v);
  v = h2fma(hy1, rv[i + 5], v);
  v = h2fma(hy0, rv[i + 6], v);
  return v;
}

// Store 8 D values (fp16x2 each) for one slot; layout warp-contiguous:
// slot*2048 + half*1024 + tid*4 -> 128B coalescing per warp.
__device__ __forceinline__ void store_slot(u32* __restrict__ dst,
                                           const u32 D[8]) {
  ((uint4*)dst)[0] = make_uint4(D[0], D[1], D[2], D[3]);
  ((uint4*)(dst + 1024))[0] = make_uint4(D[4], D[5], D[6], D[7]);
}

extern "C" __global__ void __launch_bounds__(NTHREADS, 2)
mind_main(const float* __restrict__ pred, const float* __restrict__ gt,
          float* __restrict__ out) {
  extern __shared__ u64 smem[];
  u64* sImg = smem;
  u32* bufbase = (u32*)(smem + RH * IP);
  u32* buf[NBUF];
#pragma unroll
  for (int i = 0; i < NBUF; i++) buf[i] = bufbase + i * BROWS * BP;

  const int tX = blockIdx.x, tY = blockIdx.y, b = blockIdx.z;
  const int tid = threadIdx.x;
  const int ctaIdx = (b * TILES_Y + tY) * TILES_X + tX;
  u32* myD = g_D + (size_t)ctaIdx * CTA_U32 + tid * 4;
  const float* imgP = pred + b * HIMG * WIMG;
  const float* imgG = gt + b * HIMG * WIMG;

  // Load tile + halo (circular wrap). abs row = tY*32 + mr,
  // abs col = tX*64 + mc - 4 (both mod 384).
  float2* sImgF = (float2*)sImg;
  for (int i = tid; i < RH * RW; i += NTHREADS) {
    int mr = i / RW, mc = i - mr * RW;
    int gr = tY * TILE_H + mr; if (gr >= HIMG) gr -= HIMG;
    int gc = tX * TILE_W + mc - 4;
    if (gc < 0) gc += WIMG;
    if (gc >= WIMG) gc -= WIMG;
    sImgF[mr * IP + mc] = make_float2(imgP[gr * WIMG + gc],
                                      imgG[gr * WIMG + gc]);
  }
  __syncthreads();

  // Row-stage: 252 width-12 units = 42 buffer rows x 6 blocks.
  const bool rowAct = tid < 252;
  const int r1 = tid % 42;
  const int j1 = (tid / 42) * 12;

  // Col-stage: 64 cols x 4 groups of 8 rows (all 256 threads).
  const int cc = tid & 63;
  const int gg = tid >> 6;
  const int rbase = gg * 8;
  const int cc4 = cc + 4;           // buffer col of pixel col cc
  const bool cOK = (tX * TILE_W + cc) < INNER;
  const int py0 = tY * TILE_H + rbase;

  const u64 gx0 = bcast2(GX0), gx1 = bcast2(GX1), gx2 = bcast2(GX2);
  const u32 hy0 = bch2(GY0), hy1 = bch2(GY1), hy2 = bch2(GY2),
            hy3 = bch2(GY3);

  u32 Dmin16[8];
  float Vp[8], Vg[8];
#pragma unroll
  for (int i = 0; i < 8; i++) {
    Dmin16[i] = 0x7BFF7BFFu;   // packed fp16 max-finite
    Vp[i] = 0.f; Vg[i] = 0.f;
  }

  // -------- Pass A: D fields -> gmem slots; Dmin + cardinal V --------
  // 6 buffers: iteration g consumes events {3g..3g+2} from bank (g&1)*3,
  // produces events {3g+3..3g+5} into the other bank. 20 barriers.
#pragma unroll
  for (int ee = 0; ee < 3; ee++) {
    int sx, sy; bool isPair;
    decode_event(ee, sx, sy, isPair);
    if (rowAct) produce_unit(sImg, buf[ee], r1, j1, sx, sy, gx0, gx1, gx2);
  }
  __syncthreads();

  for (int g = 0; g < NGROUPS; g++) {
    const int setc = (g & 1) * 3;
#pragma unroll
    for (int ee = 0; ee < 3; ee++) {
      const int e = 3 * g + ee;
      if (e < NEVENTS) {
        int sx, sy; bool isPair;
        decode_event(e, sx, sy, isPair);
        const u32* bc = buf[setc + ee];
        u32 rv[14];
#pragma unroll
        for (int i = 0; i < 14; i++) rv[i] = bc[(rbase + i) * BP + cc4];
        u32 D1[8];
#pragma unroll
        for (int i = 0; i < 8; i++) D1[i] = col7h(rv, i, hy0, hy1, hy2, hy3);
        store_slot(myD + e * SLOT_U32, D1);
        if (isPair) {
          const u32* bp2 = bc + sy * BP + sx;
#pragma unroll
          for (int i = 0; i < 14; i++) rv[i] = bp2[(rbase + i) * BP + cc4];
          u32 D2[8];
#pragma unroll
          for (int i = 0; i < 8; i++)
            D2[i] = col7h(rv, i, hy0, hy1, hy2, hy3);
          store_slot(myD + (NEVENTS + e) * SLOT_U32, D2);
#pragma unroll
          for (int i = 0; i < 8; i++) {
            Dmin16[i] = h2min(Dmin16[i], h2min(D1[i], D2[i]));
            if (e == 0) {            // pair (1,0): V = D(-1,0) + D(1,0)
              float p1, g1, p2, g2;
              h2up(D1[i], p1, g1); h2up(D2[i], p2, g2);
              Vp[i] = p2 + p1; Vg[i] = g2 + g1;
            } else if (e == 8) {     // pair (0,1): V = (V + D(0,-1)) + D(0,1)
              float p1, g1, p2, g2;
              h2up(D1[i], p1, g1); h2up(D2[i], p2, g2);
              Vp[i] = (Vp[i] + p2) + p1; Vg[i] = (Vg[i] + g2) + g1;
            }
          }
        } else {
#pragma unroll
          for (int i = 0; i < 8; i++) Dmin16[i] = h2min(Dmin16[i], D1[i]);
        }
      }
    }
    const int setp = ((g + 1) & 1) * 3;
#pragma unroll
    for (int ee = 0; ee < 3; ee++) {
      const int e = 3 * g + 3 + ee;
      if (e < NEVENTS) {
        int sx, sy; bool isPair;
        decode_event(e, sx, sy, isPair);
        if (rowAct && (isPair || r1 < 38))
          produce_unit(sImg, buf[setp + ee], r1, j1, sx, sy, gx0, gx1, gx2);
      }
    }
    __syncthreads();
  }

  // Fold validity mask into invV: masked pixels get invV = 0, so their
  // term is |exp(0) - exp(0)| = 0 and contributes nothing.
  float ivp[8], ivg[8];
#pragma unroll
  for (int i = 0; i < 8; i++) {
    const bool ok = cOK && (py0 + i) < INNER;
    ivp[i] = ok ? (LOG2E / (Vp[i] * 0.25f + 1e-5f)) : 0.f;
    ivg[i] = ok ? (LOG2E / (Vg[i] * 0.25f + 1e-5f)) : 0.f;
  }

  // -------- Pass B: stream D back in REVERSE write order (recent slots
  // still L2-resident). Same thread, same addresses -> program order,
  // no fences, no barriers. ONE packed ex2.approx.f16x2 per slot-pixel. ----
  float acc = 0.f;
#pragma unroll 4
  for (int s = 0; s < NSLOTS; s++) {
    const u32* p = myD + (size_t)(NSLOTS - 1 - s) * SLOT_U32;
    uint4 lo = ((const uint4*)p)[0];
    uint4 hi = ((const uint4*)(p + 1024))[0];
    u32 Ds[8] = {lo.x, lo.y, lo.z, lo.w, hi.x, hi.y, hi.z, hi.w};
#pragma unroll
    for (int i = 0; i < 8; i++) {
      u32 t = h2sub(Dmin16[i], Ds[i]);   // <= 0 by construction
      float a1, b1; h2up(t, a1, b1);
      u32 m2 = ex2h2(pkh2(a1 * ivp[i], b1 * ivg[i]));  // (Mp, Mg) packed
      float mp, mg; h2up(m2, mp, mg);
      acc += fabsf(mp - mg);
    }
  }

  // ---------------- Per-CTA reduction (deterministic) ----------------
#pragma unroll
  for (int o = 16; o > 0; o >>= 1) acc += __shfl_down_sync(0xffffffffu, acc, o);
  __syncthreads();             // all pass-A smem use done
  float* red = (float*)smem;
  if ((tid & 31) == 0) red[tid >> 5] = acc;
  __syncthreads();
  if (tid == 0) {
    float s = 0.f;
#pragma unroll
    for (int ww = 0; ww < NTHREADS / 32; ww++) s += red[ww];
    g_partials[ctaIdx] = s;
    __threadfence();
    unsigned int old = atomicAdd(&g_count, 1u);
    red[8] = (old == NCTAS - 1) ? 1.f : 0.f;
  }
  __syncthreads();

  // ---------------- Last CTA: global reduction ----------------
  if (red[8] != 0.f) {
    __threadfence();
    float s = g_partials[tid];
    if (tid < NCTAS - NTHREADS) s += g_partials[tid + NTHREADS];
#pragma unroll
    for (int o = 16; o > 0; o >>= 1) s += __shfl_down_sync(0xffffffffu, s, o);
    __syncthreads();
    if ((tid & 31) == 0) red[tid >> 5] = s;
    __syncthreads();
    if (tid == 0) {
      float t = 0.f;
#pragma unroll
      for (int ww = 0; ww < NTHREADS / 32; ww++) t += red[ww];
      out[0] = t * (float)(1.0 / ((double)BATCH * INNER * INNER * 99.0));
      g_count = 0;   // reset for next graph replay
    }
  }
}

extern "C" void kernel_launch(void* const* d_in, const int* in_sizes, int n_in,
                              void* d_out, int out_size) {
  const float* pred = (const float*)d_in[0];
  const float* gt = (const float*)d_in[1];
  cudaFuncSetAttribute(mind_main, cudaFuncAttributeMaxDynamicSharedMemorySize,
                       SMEM_BYTES);
  dim3 grid(TILES_X, TILES_Y, BATCH);
  mind_main<<<grid, NTHREADS, SMEM_BYTES>>>(pred, gt, (float*)d_out);
}

// round 13
// speedup vs baseline: 1.6824x; 1.0729x over previous
#include <cuda_runtime.h>

// ---------------------------------------------------------------------------
// MIND loss, fused, single kernel. R13 = R12 +
//  - pass B reads slots in TRUE reverse-write order (singles 58..40 first,
//    then pair slots newest-first) with __ldcs (evict-first: each line is
//    dead after one read, don't thrash unread scratch out of L2)
//  - produce trimmed: pair events only produce rows < 38+sy
//  - dual accumulators in pass B
// Pass A: row conv (f32x2) -> fp16x2 smem buffer, col conv (f16x2) -> D;
//   Dmin via min.f16x2 + cardinal V in reference fp order; every D stored
//   (fp16x2 P,G) to __device__ scratch (99 slots/px). 6 buffers, 3 events
//   per barrier. Pass B: barrier-free streaming epilogue, packed ex2.f16x2.
// ---------------------------------------------------------------------------

typedef unsigned long long u64;
typedef unsigned int u32;

namespace {
constexpr int HIMG = 384;
constexpr int WIMG = 384;
constexpr int BATCH = 4;
constexpr int INNER = 370;          // 384 - 2*7
constexpr int TILE_H = 32;
constexpr int TILE_W = 64;
constexpr int RH = 47;              // img tile rows (q_r in [-7, 39])
constexpr int RW = 86;              // img tile cols (q_c in [-11, 74])
constexpr int IP = 87;              // img pitch in u64 (odd)
constexpr int BROWS = 42;           // buffer rows (q_r in [-3, 38])
constexpr int BP = 73;              // buffer pitch in b32 (odd)
constexpr int NTHREADS = 256;
constexpr int TILES_X = 6;
constexpr int TILES_Y = 12;
constexpr int NCTAS = BATCH * TILES_X * TILES_Y;   // 288 -> one wave @ occ 2
constexpr int NBUF = 6;             // 3 events per barrier, double-banked
constexpr int SMEM_BYTES = RH * IP * 8 + NBUF * BROWS * BP * 4;  // 106296 B
constexpr int NEVENTS = 59;         // 40 pairs + 19 singles
constexpr int NGROUPS = 20;         // ceil(59/3)
constexpr int NSLOTS = 99;          // stored D slots per pixel
constexpr int SLOT_U32 = TILE_H * TILE_W;          // 2048 per slot per CTA
constexpr size_t CTA_U32 = (size_t)NSLOTS * SLOT_U32;

constexpr double E98 = 0.32465246735834974;   // exp(-9/8)
constexpr double E48 = 0.60653065971263342;   // exp(-4/8)
constexpr double E18 = 0.88249690258459546;   // exp(-1/8)
constexpr double TPS = 25.132741228718345;    // 8*pi
constexpr float GX0 = (float)E98;
constexpr float GX1 = (float)E48;
constexpr float GX2 = (float)E18;             // center tap == 1
constexpr float GY0 = (float)(E98 / TPS);
constexpr float GY1 = (float)(E48 / TPS);
constexpr float GY2 = (float)(E18 / TPS);
constexpr float GY3 = (float)(1.0 / TPS);
constexpr float LOG2E = 1.4426950408889634f;
}  // namespace

__device__ u32 g_D[(size_t)NCTAS * CTA_U32];   // 233.6 MB scratch
__device__ float g_partials[NCTAS];
__device__ unsigned int g_count = 0;

// ---- packed f32x2 helpers (sm_100+) ----
__device__ __forceinline__ u64 bcast2(float x) {
  u64 r; asm("mov.b64 %0,{%1,%1};" : "=l"(r) : "f"(x)); return r;
}
__device__ __forceinline__ void up2(u64 v, float& a, float& b) {
  asm("mov.b64 {%0,%1},%2;" : "=f"(a), "=f"(b) : "l"(v));
}
__device__ __forceinline__ u64 f2sub(u64 a, u64 b) {
  u64 r; asm("sub.rn.f32x2 %0,%1,%2;" : "=l"(r) : "l"(a), "l"(b)); return r;
}
__device__ __forceinline__ u64 f2mul(u64 a, u64 b) {
  u64 r; asm("mul.rn.f32x2 %0,%1,%2;" : "=l"(r) : "l"(a), "l"(b)); return r;
}
__device__ __forceinline__ u64 f2add(u64 a, u64 b) {
  u64 r; asm("add.rn.f32x2 %0,%1,%2;" : "=l"(r) : "l"(a), "l"(b)); return r;
}
__device__ __forceinline__ u64 f2fma(u64 a, u64 b, u64 c) {
  u64 r; asm("fma.rn.f32x2 %0,%1,%2,%3;" : "=l"(r) : "l"(a), "l"(b), "l"(c));
  return r;
}

// ---- packed f16x2 helpers ----
__device__ __forceinline__ u32 bch2(float x) {
  u32 r; asm("cvt.rn.f16x2.f32 %0,%1,%1;" : "=r"(r) : "f"(x)); return r;
}
__device__ __forceinline__ u32 f2h2(u64 v) {     // f32x2 -> f16x2 (lo=P)
  float a, b; up2(v, a, b);
  u32 r; asm("cvt.rn.f16x2.f32 %0,%1,%2;" : "=r"(r) : "f"(b), "f"(a));
  return r;
}
__device__ __forceinline__ u32 pkh2(float lo, float hi) {
  u32 r; asm("cvt.rn.f16x2.f32 %0,%1,%2;" : "=r"(r) : "f"(hi), "f"(lo));
  return r;
}
__device__ __forceinline__ void h2up(u32 v, float& a, float& b) {
  asm("{\n\t.reg .b16 l,h;\n\tmov.b32 {l,h},%2;\n\t"
      "cvt.f32.f16 %0,l;\n\tcvt.f32.f16 %1,h;\n\t}"
      : "=f"(a), "=f"(b) : "r"(v));
}
__device__ __forceinline__ u32 h2mul(u32 a, u32 b) {
  u32 r; asm("mul.rn.f16x2 %0,%1,%2;" : "=r"(r) : "r"(a), "r"(b)); return r;
}
__device__ __forceinline__ u32 h2fma(u32 a, u32 b, u32 c) {
  u32 r; asm("fma.rn.f16x2 %0,%1,%2,%3;" : "=r"(r) : "r"(a), "r"(b), "r"(c));
  return r;
}
__device__ __forceinline__ u32 h2min(u32 a, u32 b) {
  u32 r; asm("min.f16x2 %0,%1,%2;" : "=r"(r) : "r"(a), "r"(b)); return r;
}
__device__ __forceinline__ u32 h2sub(u32 a, u32 b) {
  u32 r; asm("sub.rn.f16x2 %0,%1,%2;" : "=r"(r) : "r"(a), "r"(b)); return r;
}
__device__ __forceinline__ u32 ex2h2(u32 x) {    // packed exp2, 1 MUFU op
  u32 r; asm("ex2.approx.f16x2 %0,%1;" : "=r"(r) : "r"(x)); return r;
}

// Event schedule. e<40: pair representatives (sy>0, or sy==0 && sx>=1);
// each also yields -s. e in [40,50): sx=-5 singles; [50,59): sy=-5 singles.
// Pair (1,0) at e=0 and (0,1) at e=8 -> V accumulates in reference order.
__device__ __forceinline__ void decode_event(int e, int& sx, int& sy,
                                             bool& pair) {
  if (e < 4)       { sx = e + 1;               sy = 0;            pair = true; }
  else if (e < 40) { int t = e - 4; sy = 1 + t / 9; sx = t % 9 - 4;
                     pair = true; }
  else if (e < 50) { sx = -5;                  sy = (e - 40) - 5; pair = false; }
  else             { sy = -5;                  sx = (e - 50) - 4; pair = false; }
}

// Fused diffsq + horizontal 7-tap conv (f32x2), fp16x2 store.
__device__ __forceinline__ void produce_unit(const u64* __restrict__ sImg,
                                             u32* __restrict__ Bdst,
                                             int r1, int j1, int sx, int sy,
                                             u64 gx0, u64 gx1, u64 gx2) {
  const u64* pa = sImg + (r1 + 4) * IP + (j1 + 4);
  const u64* pb = sImg + (r1 + 4 - sy) * IP + (j1 + 4 - sx);
  u64 dsq[18];
#pragma unroll
  for (int k = 0; k < 18; k++) {
    u64 d = f2sub(pa[k], pb[k]);
    dsq[k] = f2mul(d, d);
  }
  u32* pr = Bdst + r1 * BP + j1;
#pragma unroll
  for (int c = 0; c < 12; c++) {
    u64 v = f2mul(gx0, dsq[c]);
    v = f2fma(gx1, dsq[c + 1], v);
    v = f2fma(gx2, dsq[c + 2], v);
    v = f2add(v, dsq[c + 3]);  // center tap weight == 1
    v = f2fma(gx2, dsq[c + 4], v);
    v = f2fma(gx1, dsq[c + 5], v);
    v = f2fma(gx0, dsq[c + 6], v);
    pr[c] = f2h2(v);
  }
}

__device__ __forceinline__ u32 col7h(const u32* rv, int i,
                                     u32 hy0, u32 hy1, u32 hy2, u32 hy3) {
  u32 v = h2mul(hy0, rv[i]);
  v = h2fma(hy1, rv[i + 1], v);
  v = h2fma(hy2, rv[i + 2], v);
  v = h2fma(hy3, rv[i + 3], v);
  v = h2fma(hy2, rv[i + 4], v);
  v = h2fma(hy1, rv[i + 5], v);
  v = h2fma(hy0, rv[i + 6], v);
  return v;
}

// Store 8 D values (fp16x2 each) for one slot; layout warp-contiguous:
// slot*2048 + half*1024 + tid*4 -> 128B coalescing per warp.
__device__ __forceinline__ void store_slot(u32* __restrict__ dst,
                                           const u32 D[8]) {
  ((uint4*)dst)[0] = make_uint4(D[0], D[1], D[2], D[3]);
  ((uint4*)(dst + 1024))[0] = make_uint4(D[4], D[5], D[6], D[7]);
}

extern "C" __global__ void __launch_bounds__(NTHREADS, 2)
mind_main(const float* __restrict__ pred, const float* __restrict__ gt,
          float* __restrict__ out) {
  extern __shared__ u64 smem[];
  u64* sImg = smem;
  u32* bufbase = (u32*)(smem + RH * IP);
  u32* buf[NBUF];
#pragma unroll
  for (int i = 0; i < NBUF; i++) buf[i] = bufbase + i * BROWS * BP;

  const int tX = blockIdx.x, tY = blockIdx.y, b = blockIdx.z;
  const int tid = threadIdx.x;
  const int ctaIdx = (b * TILES_Y + tY) * TILES_X + tX;
  u32* myD = g_D + (size_t)ctaIdx * CTA_U32 + tid * 4;
  const float* imgP = pred + b * HIMG * WIMG;
  const float* imgG = gt + b * HIMG * WIMG;

  // Load tile + halo (circular wrap). abs row = tY*32 + mr,
  // abs col = tX*64 + mc - 4 (both mod 384).
  float2* sImgF = (float2*)sImg;
  for (int i = tid; i < RH * RW; i += NTHREADS) {
    int mr = i / RW, mc = i - mr * RW;
    int gr = tY * TILE_H + mr; if (gr >= HIMG) gr -= HIMG;
    int gc = tX * TILE_W + mc - 4;
    if (gc < 0) gc += WIMG;
    if (gc >= WIMG) gc -= WIMG;
    sImgF[mr * IP + mc] = make_float2(imgP[gr * WIMG + gc],
                                      imgG[gr * WIMG + gc]);
  }
  __syncthreads();

  // Row-stage: width-12 units = 42 buffer rows x 6 blocks.
  const bool rowAct = tid < 252;
  const int r1 = tid % 42;
  const int j1 = (tid / 42) * 12;

  // Col-stage: 64 cols x 4 groups of 8 rows (all 256 threads).
  const int cc = tid & 63;
  const int gg = tid >> 6;
  const int rbase = gg * 8;
  const int cc4 = cc + 4;           // buffer col of pixel col cc
  const bool cOK = (tX * TILE_W + cc) < INNER;
  const int py0 = tY * TILE_H + rbase;

  const u64 gx0 = bcast2(GX0), gx1 = bcast2(GX1), gx2 = bcast2(GX2);
  const u32 hy0 = bch2(GY0), hy1 = bch2(GY1), hy2 = bch2(GY2),
            hy3 = bch2(GY3);

  u32 Dmin16[8];
  float Vp[8], Vg[8];
#pragma unroll
  for (int i = 0; i < 8; i++) {
    Dmin16[i] = 0x7BFF7BFFu;   // packed fp16 max-finite
    Vp[i] = 0.f; Vg[i] = 0.f;
  }

  // -------- Pass A: D fields -> gmem slots; Dmin + cardinal V --------
  // 6 buffers: iteration g consumes events {3g..3g+2} from bank (g&1)*3,
  // produces events {3g+3..3g+5} into the other bank. 20 barriers.
  // Produce trim: pair event needs rows < 38+sy (D2 read offset), single 38.
#pragma unroll
  for (int ee = 0; ee < 3; ee++) {
    int sx, sy; bool isPair;
    decode_event(ee, sx, sy, isPair);
    if (rowAct && r1 < 38 + (isPair ? sy : 0))
      produce_unit(sImg, buf[ee], r1, j1, sx, sy, gx0, gx1, gx2);
  }
  __syncthreads();

  for (int g = 0; g < NGROUPS; g++) {
    const int setc = (g & 1) * 3;
#pragma unroll
    for (int ee = 0; ee < 3; ee++) {
      const int e = 3 * g + ee;
      if (e < NEVENTS) {
        int sx, sy; bool isPair;
        decode_event(e, sx, sy, isPair);
        const u32* bc = buf[setc + ee];
        u32 rv[14];
#pragma unroll
        for (int i = 0; i < 14; i++) rv[i] = bc[(rbase + i) * BP + cc4];
        u32 D1[8];
#pragma unroll
        for (int i = 0; i < 8; i++) D1[i] = col7h(rv, i, hy0, hy1, hy2, hy3);
        store_slot(myD + e * SLOT_U32, D1);
        if (isPair) {
          const u32* bp2 = bc + sy * BP + sx;
#pragma unroll
          for (int i = 0; i < 14; i++) rv[i] = bp2[(rbase + i) * BP + cc4];
          u32 D2[8];
#pragma unroll
          for (int i = 0; i < 8; i++)
            D2[i] = col7h(rv, i, hy0, hy1, hy2, hy3);
          store_slot(myD + (NEVENTS + e) * SLOT_U32, D2);
#pragma unroll
          for (int i = 0; i < 8; i++) {
            Dmin16[i] = h2min(Dmin16[i], h2min(D1[i], D2[i]));
            if (e == 0) {            // pair (1,0): V = D(-1,0) + D(1,0)
              float p1, g1, p2, g2;
              h2up(D1[i], p1, g1); h2up(D2[i], p2, g2);
              Vp[i] = p2 + p1; Vg[i] = g2 + g1;
            } else if (e == 8) {     // pair (0,1): V = (V + D(0,-1)) + D(0,1)
              float p1, g1, p2, g2;
              h2up(D1[i], p1, g1); h2up(D2[i], p2, g2);
              Vp[i] = (Vp[i] + p2) + p1; Vg[i] = (Vg[i] + g2) + g1;
            }
          }
        } else {
#pragma unroll
          for (int i = 0; i < 8; i++) Dmin16[i] = h2min(Dmin16[i], D1[i]);
        }
      }
    }
    const int setp = ((g + 1) & 1) * 3;
#pragma unroll
    for (int ee = 0; ee < 3; ee++) {
      const int e = 3 * g + 3 + ee;
      if (e < NEVENTS) {
        int sx, sy; bool isPair;
        decode_event(e, sx, sy, isPair);
        if (rowAct && r1 < 38 + (isPair ? sy : 0))
          produce_unit(sImg, buf[setp + ee], r1, j1, sx, sy, gx0, gx1, gx2);
      }
    }
    __syncthreads();
  }

  // Fold validity mask into invV: masked pixels get invV = 0, so their
  // term is |exp(0) - exp(0)| = 0 and contributes nothing.
  float ivp[8], ivg[8];
#pragma unroll
  for (int i = 0; i < 8; i++) {
    const bool ok = cOK && (py0 + i) < INNER;
    ivp[i] = ok ? (LOG2E / (Vp[i] * 0.25f + 1e-5f)) : 0.f;
    ivg[i] = ok ? (LOG2E / (Vg[i] * 0.25f + 1e-5f)) : 0.f;
  }

  // -------- Pass B: stream D back in TRUE reverse-write order --------
  // Write order was: e=0:(slot0,slot59), e=1:(slot1,slot60), ...,
  // e=39:(slot39,slot98), then singles e=40..58 -> slots 40..58.
  // Read newest-first: slots 58..40, then (98,39),(97,38),...,(59,0).
  // __ldcs: each line is read exactly once -> evict-first, keep unread
  // scratch resident. Same thread wrote these addresses -> program order.
  float acc0 = 0.f, acc1 = 0.f;
#pragma unroll 4
  for (int k = 0; k < NSLOTS; k++) {
    int slot;
    if (k < 19) {
      slot = 58 - k;                      // singles, newest first
    } else {
      int t = k - 19;
      int e = 39 - (t >> 1);
      slot = (t & 1) ? e : (NEVENTS + e); // D2 slot then D1 slot per event
    }
    const u32* p = myD + (size_t)slot * SLOT_U32;
    uint4 lo = __ldcs((const uint4*)p);
    uint4 hi = __ldcs((const uint4*)(p + 1024));
    u32 Ds[8] = {lo.x, lo.y, lo.z, lo.w, hi.x, hi.y, hi.z, hi.w};
#pragma unroll
    for (int i = 0; i < 8; i++) {
      u32 t16 = h2sub(Dmin16[i], Ds[i]);  // <= 0 by construction
      float a1, b1; h2up(t16, a1, b1);
      u32 m2 = ex2h2(pkh2(a1 * ivp[i], b1 * ivg[i]));  // (Mp, Mg) packed
      float mp, mg; h2up(m2, mp, mg);
      if (i & 1) acc1 += fabsf(mp - mg); else acc0 += fabsf(mp - mg);
    }
  }
  float acc = acc0 + acc1;

  // ---------------- Per-CTA reduction (deterministic) ----------------
#pragma unroll
  for (int o = 16; o > 0; o >>= 1) acc += __shfl_down_sync(0xffffffffu, acc, o);
  __syncthreads();             // all pass-A smem use done
  float* red = (float*)smem;
  if ((tid & 31) == 0) red[tid >> 5] = acc;
  __syncthreads();
  if (tid == 0) {
    float s = 0.f;
#pragma unroll
    for (int ww = 0; ww < NTHREADS / 32; ww++) s += red[ww];
    g_partials[ctaIdx] = s;
    __threadfence();
    unsigned int old = atomicAdd(&g_count, 1u);
    red[8] = (old == NCTAS - 1) ? 1.f : 0.f;
  }
  __syncthreads();

  // ---------------- Last CTA: global reduction ----------------
  if (red[8] != 0.f) {
    __threadfence();
    float s = g_partials[tid];
    if (tid < NCTAS - NTHREADS) s += g_partials[tid + NTHREADS];
#pragma unroll
    for (int o = 16; o > 0; o >>= 1) s += __shfl_down_sync(0xffffffffu, s, o);
    __syncthreads();
    if ((tid & 31) == 0) red[tid >> 5] = s;
    __syncthreads();
    if (tid == 0) {
      float t = 0.f;
#pragma unroll
      for (int ww = 0; ww < NTHREADS / 32; ww++) t += red[ww];
      out[0] = t * (float)(1.0 / ((double)BATCH * INNER * INNER * 99.0));
      g_count = 0;   // reset for next graph replay
    }
  }
}

extern "C" void kernel_launch(void* const* d_in, const int* in_sizes, int n_in,
                              void* d_out, int out_size) {
  const float* pred = (const float*)d_in[0];
  const float* gt = (const float*)d_in[1];
  cudaFuncSetAttribute(mind_main, cudaFuncAttributeMaxDynamicSharedMemorySize,
                       SMEM_BYTES);
  dim3 grid(TILES_X, TILES_Y, BATCH);
  mind_main<<<grid, NTHREADS, SMEM_BYTES>>>(pred, gt, (float*)d_out);
}

// round 14
// speedup vs baseline: 1.9162x; 1.1390x over previous
#include <cuda_runtime.h>

// ---------------------------------------------------------------------------
// MIND loss, fused, single kernel. R14 = R13 +
//  - image tile stored as fp16x2 (P,G): row stage is pure HFMA2, half the
//    LDS bytes, no cvt at buffer store
//  - unshifted taps pa[18] cached in registers (shift-invariant, reused for
//    all 59 events): row-stage smem loads drop 72 -> 18 wavefronts/warp-event
// Pipeline: pass A (20 barriers): fused diffsq + 7-tap row conv (f16x2) ->
//   smem buffer, 7-tap col conv (f16x2) -> D; Dmin via min.f16x2, cardinal V
//   in reference fp order; every D stored (fp16x2) to __device__ scratch.
// Pass B (barrier-free): reverse-write-order __ldcs streaming + ex2.f16x2.
// ---------------------------------------------------------------------------

typedef unsigned int u32;

namespace {
constexpr int HIMG = 384;
constexpr int WIMG = 384;
constexpr int BATCH = 4;
constexpr int INNER = 370;          // 384 - 2*7
constexpr int TILE_H = 32;
constexpr int TILE_W = 64;
constexpr int RH = 47;              // img tile rows (q_r in [-7, 39])
constexpr int RW = 86;              // img tile cols (q_c in [-11, 74])
constexpr int IP = 87;              // img pitch in u32 (odd)
constexpr int BROWS = 42;           // buffer rows (q_r in [-3, 38])
constexpr int BP = 73;              // buffer pitch in u32 (odd)
constexpr int NTHREADS = 256;
constexpr int TILES_X = 6;
constexpr int TILES_Y = 12;
constexpr int NCTAS = BATCH * TILES_X * TILES_Y;   // 288 -> one wave @ occ 2
constexpr int NBUF = 6;             // 3 events per barrier, double-banked
constexpr int SMEM_BYTES = RH * IP * 4 + NBUF * BROWS * BP * 4;  // 89940 B
constexpr int NEVENTS = 59;         // 40 pairs + 19 singles
constexpr int NGROUPS = 20;         // ceil(59/3)
constexpr int NSLOTS = 99;          // stored D slots per pixel
constexpr int SLOT_U32 = TILE_H * TILE_W;          // 2048 per slot per CTA
constexpr size_t CTA_U32 = (size_t)NSLOTS * SLOT_U32;

constexpr double E98 = 0.32465246735834974;   // exp(-9/8)
constexpr double E48 = 0.60653065971263342;   // exp(-4/8)
constexpr double E18 = 0.88249690258459546;   // exp(-1/8)
constexpr double TPS = 25.132741228718345;    // 8*pi
constexpr float GX0 = (float)E98;
constexpr float GX1 = (float)E48;
constexpr float GX2 = (float)E18;             // center tap == 1
constexpr float GY0 = (float)(E98 / TPS);
constexpr float GY1 = (float)(E48 / TPS);
constexpr float GY2 = (float)(E18 / TPS);
constexpr float GY3 = (float)(1.0 / TPS);
constexpr float LOG2E = 1.4426950408889634f;
}  // namespace

__device__ u32 g_D[(size_t)NCTAS * CTA_U32];   // 233.6 MB scratch
__device__ float g_partials[NCTAS];
__device__ unsigned int g_count = 0;

// ---- packed f16x2 helpers ----
__device__ __forceinline__ u32 bch2(float x) {
  u32 r; asm("cvt.rn.f16x2.f32 %0,%1,%1;" : "=r"(r) : "f"(x)); return r;
}
__device__ __forceinline__ u32 pkh2(float lo, float hi) {
  u32 r; asm("cvt.rn.f16x2.f32 %0,%1,%2;" : "=r"(r) : "f"(hi), "f"(lo));
  return r;
}
__device__ __forceinline__ void h2up(u32 v, float& a, float& b) {
  asm("{\n\t.reg .b16 l,h;\n\tmov.b32 {l,h},%2;\n\t"
      "cvt.f32.f16 %0,l;\n\tcvt.f32.f16 %1,h;\n\t}"
      : "=f"(a), "=f"(b) : "r"(v));
}
__device__ __forceinline__ u32 h2mul(u32 a, u32 b) {
  u32 r; asm("mul.rn.f16x2 %0,%1,%2;" : "=r"(r) : "r"(a), "r"(b)); return r;
}
__device__ __forceinline__ u32 h2add(u32 a, u32 b) {
  u32 r; asm("add.rn.f16x2 %0,%1,%2;" : "=r"(r) : "r"(a), "r"(b)); return r;
}
__device__ __forceinline__ u32 h2fma(u32 a, u32 b, u32 c) {
  u32 r; asm("fma.rn.f16x2 %0,%1,%2,%3;" : "=r"(r) : "r"(a), "r"(b), "r"(c));
  return r;
}
__device__ __forceinline__ u32 h2min(u32 a, u32 b) {
  u32 r; asm("min.f16x2 %0,%1,%2;" : "=r"(r) : "r"(a), "r"(b)); return r;
}
__device__ __forceinline__ u32 h2sub(u32 a, u32 b) {
  u32 r; asm("sub.rn.f16x2 %0,%1,%2;" : "=r"(r) : "r"(a), "r"(b)); return r;
}
__device__ __forceinline__ u32 ex2h2(u32 x) {    // packed exp2, 1 MUFU op
  u32 r; asm("ex2.approx.f16x2 %0,%1;" : "=r"(r) : "r"(x)); return r;
}

// Event schedule. e<40: pair representatives (sy>0, or sy==0 && sx>=1);
// each also yields -s. e in [40,50): sx=-5 singles; [50,59): sy=-5 singles.
// Pair (1,0) at e=0 and (0,1) at e=8 -> V accumulates in reference order.
__device__ __forceinline__ void decode_event(int e, int& sx, int& sy,
                                             bool& pair) {
  if (e < 4)       { sx = e + 1;               sy = 0;            pair = true; }
  else if (e < 40) { int t = e - 4; sy = 1 + t / 9; sx = t % 9 - 4;
                     pair = true; }
  else if (e < 50) { sx = -5;                  sy = (e - 40) - 5; pair = false; }
  else             { sy = -5;                  sx = (e - 50) - 4; pair = false; }
}

// Fused diffsq + horizontal 7-tap conv, all f16x2. pa from registers.
__device__ __forceinline__ void produce_unit(const u32 paR[18],
                                             const u32* __restrict__ sImgH,
                                             u32* __restrict__ Bdst,
                                             int r1, int j1, int sx, int sy,
                                             u32 hx0, u32 hx1, u32 hx2) {
  const u32* pb = sImgH + (r1 + 4 - sy) * IP + (j1 + 4 - sx);
  u32 dsq[18];
#pragma unroll
  for (int k = 0; k < 18; k++) {
    u32 d = h2sub(paR[k], pb[k]);
    dsq[k] = h2mul(d, d);
  }
  u32* pr = Bdst + r1 * BP + j1;
#pragma unroll
  for (int c = 0; c < 12; c++) {
    u32 v = h2mul(hx0, dsq[c]);
    v = h2fma(hx1, dsq[c + 1], v);
    v = h2fma(hx2, dsq[c + 2], v);
    v = h2add(v, dsq[c + 3]);  // center tap weight == 1
    v = h2fma(hx2, dsq[c + 4], v);
    v = h2fma(hx1, dsq[c + 5], v);
    v = h2fma(hx0, dsq[c + 6], v);
    pr[c] = v;
  }
}

__device__ __forceinline__ u32 col7h(const u32* rv, int i,
                                     u32 hy0, u32 hy1, u32 hy2, u32 hy3) {
  u32 v = h2mul(hy0, rv[i]);
  v = h2fma(hy1, rv[i + 1], v);
  v = h2fma(hy2, rv[i + 2], v);
  v = h2fma(hy3, rv[i + 3], v);
  v = h2fma(hy2, rv[i + 4], v);
  v = h2fma(hy1, rv[i + 5], v);
  v = h2fma(hy0, rv[i + 6], v);
  return v;
}

// Store 8 D values (fp16x2 each) for one slot; layout warp-contiguous:
// slot*2048 + half*1024 + tid*4 -> 128B coalescing per warp.
__device__ __forceinline__ void store_slot(u32* __restrict__ dst,
                                           const u32 D[8]) {
  ((uint4*)dst)[0] = make_uint4(D[0], D[1], D[2], D[3]);
  ((uint4*)(dst + 1024))[0] = make_uint4(D[4], D[5], D[6], D[7]);
}

extern "C" __global__ void __launch_bounds__(NTHREADS, 2)
mind_main(const float* __restrict__ pred, const float* __restrict__ gt,
          float* __restrict__ out) {
  extern __shared__ u32 smem[];
  u32* sImgH = smem;
  u32* bufbase = smem + RH * IP;
  u32* buf[NBUF];
#pragma unroll
  for (int i = 0; i < NBUF; i++) buf[i] = bufbase + i * BROWS * BP;

  const int tX = blockIdx.x, tY = blockIdx.y, b = blockIdx.z;
  const int tid = threadIdx.x;
  const int ctaIdx = (b * TILES_Y + tY) * TILES_X + tX;
  u32* myD = g_D + (size_t)ctaIdx * CTA_U32 + tid * 4;
  const float* imgP = pred + b * HIMG * WIMG;
  const float* imgG = gt + b * HIMG * WIMG;

  // Load tile + halo (circular wrap), quantize both images to fp16x2.
  // abs row = tY*32 + mr, abs col = tX*64 + mc - 4 (both mod 384).
  for (int i = tid; i < RH * RW; i += NTHREADS) {
    int mr = i / RW, mc = i - mr * RW;
    int gr = tY * TILE_H + mr; if (gr >= HIMG) gr -= HIMG;
    int gc = tX * TILE_W + mc - 4;
    if (gc < 0) gc += WIMG;
    if (gc >= WIMG) gc -= WIMG;
    sImgH[mr * IP + mc] = pkh2(imgP[gr * WIMG + gc], imgG[gr * WIMG + gc]);
  }
  __syncthreads();

  // Row-stage: width-12 units = 42 buffer rows x 6 blocks.
  const bool rowAct = tid < 252;
  const int r1 = tid % 42;
  const int j1 = (tid / 42) * 12;

  // Cache the unshifted taps in registers (reused for all 59 events).
  u32 paR[18];
  {
    const u32* pa = sImgH + (r1 + 4) * IP + (j1 + 4);
#pragma unroll
    for (int k = 0; k < 18; k++) paR[k] = pa[k];
  }

  // Col-stage: 64 cols x 4 groups of 8 rows (all 256 threads).
  const int cc = tid & 63;
  const int gg = tid >> 6;
  const int rbase = gg * 8;
  const int cc4 = cc + 4;           // buffer col of pixel col cc
  const bool cOK = (tX * TILE_W + cc) < INNER;
  const int py0 = tY * TILE_H + rbase;

  const u32 hx0 = bch2(GX0), hx1 = bch2(GX1), hx2 = bch2(GX2);
  const u32 hy0 = bch2(GY0), hy1 = bch2(GY1), hy2 = bch2(GY2),
            hy3 = bch2(GY3);

  u32 Dmin16[8];
  float Vp[8], Vg[8];
#pragma unroll
  for (int i = 0; i < 8; i++) {
    Dmin16[i] = 0x7BFF7BFFu;   // packed fp16 max-finite
    Vp[i] = 0.f; Vg[i] = 0.f;
  }

  // -------- Pass A: D fields -> gmem slots; Dmin + cardinal V --------
  // 6 buffers: iteration g consumes events {3g..3g+2} from bank (g&1)*3,
  // produces events {3g+3..3g+5} into the other bank. 20 barriers.
  // Produce trim: pair event needs rows < 38+sy (D2 read offset), single 38.
#pragma unroll
  for (int ee = 0; ee < 3; ee++) {
    int sx, sy; bool isPair;
    decode_event(ee, sx, sy, isPair);
    if (rowAct && r1 < 38 + (isPair ? sy : 0))
      produce_unit(paR, sImgH, buf[ee], r1, j1, sx, sy, hx0, hx1, hx2);
  }
  __syncthreads();

  for (int g = 0; g < NGROUPS; g++) {
    const int setc = (g & 1) * 3;
#pragma unroll
    for (int ee = 0; ee < 3; ee++) {
      const int e = 3 * g + ee;
      if (e < NEVENTS) {
        int sx, sy; bool isPair;
        decode_event(e, sx, sy, isPair);
        const u32* bc = buf[setc + ee];
        u32 rv[14];
#pragma unroll
        for (int i = 0; i < 14; i++) rv[i] = bc[(rbase + i) * BP + cc4];
        u32 D1[8];
#pragma unroll
        for (int i = 0; i < 8; i++) D1[i] = col7h(rv, i, hy0, hy1, hy2, hy3);
        store_slot(myD + e * SLOT_U32, D1);
        if (isPair) {
          const u32* bp2 = bc + sy * BP + sx;
#pragma unroll
          for (int i = 0; i < 14; i++) rv[i] = bp2[(rbase + i) * BP + cc4];
          u32 D2[8];
#pragma unroll
          for (int i = 0; i < 8; i++)
            D2[i] = col7h(rv, i, hy0, hy1, hy2, hy3);
          store_slot(myD + (NEVENTS + e) * SLOT_U32, D2);
#pragma unroll
          for (int i = 0; i < 8; i++) {
            Dmin16[i] = h2min(Dmin16[i], h2min(D1[i], D2[i]));
            if (e == 0) {            // pair (1,0): V = D(-1,0) + D(1,0)
              float p1, g1, p2, g2;
              h2up(D1[i], p1, g1); h2up(D2[i], p2, g2);
              Vp[i] = p2 + p1; Vg[i] = g2 + g1;
            } else if (e == 8) {     // pair (0,1): V = (V + D(0,-1)) + D(0,1)
              float p1, g1, p2, g2;
              h2up(D1[i], p1, g1); h2up(D2[i], p2, g2);
              Vp[i] = (Vp[i] + p2) + p1; Vg[i] = (Vg[i] + g2) + g1;
            }
          }
        } else {
#pragma unroll
          for (int i = 0; i < 8; i++) Dmin16[i] = h2min(Dmin16[i], D1[i]);
        }
      }
    }
    const int setp = ((g + 1) & 1) * 3;
#pragma unroll
    for (int ee = 0; ee < 3; ee++) {
      const int e = 3 * g + 3 + ee;
      if (e < NEVENTS) {
        int sx, sy; bool isPair;
        decode_event(e, sx, sy, isPair);
        if (rowAct && r1 < 38 + (isPair ? sy : 0))
          produce_unit(paR, sImgH, buf[setp + ee], r1, j1, sx, sy,
                       hx0, hx1, hx2);
      }
    }
    __syncthreads();
  }

  // Fold validity mask into invV: masked pixels get invV = 0, so their
  // term is |exp(0) - exp(0)| = 0 and contributes nothing.
  float ivp[8], ivg[8];
#pragma unroll
  for (int i = 0; i < 8; i++) {
    const bool ok = cOK && (py0 + i) < INNER;
    ivp[i] = ok ? (LOG2E / (Vp[i] * 0.25f + 1e-5f)) : 0.f;
    ivg[i] = ok ? (LOG2E / (Vg[i] * 0.25f + 1e-5f)) : 0.f;
  }

  // -------- Pass B: stream D back in TRUE reverse-write order --------
  // Write order: e=0:(slot0,slot59), ..., e=39:(slot39,slot98), then
  // singles e=40..58 -> slots 40..58. Read newest-first: 58..40, then
  // (98,39),(97,38),...,(59,0). __ldcs: evict-first (each line read once).
  // Same thread wrote these addresses -> program order, no fences.
  float acc0 = 0.f, acc1 = 0.f;
#pragma unroll 4
  for (int k = 0; k < NSLOTS; k++) {
    int slot;
    if (k < 19) {
      slot = 58 - k;                      // singles, newest first
    } else {
      int t = k - 19;
      int e = 39 - (t >> 1);
      slot = (t & 1) ? e : (NEVENTS + e); // D2 slot then D1 slot per event
    }
    const u32* p = myD + (size_t)slot * SLOT_U32;
    uint4 lo = __ldcs((const uint4*)p);
    uint4 hi = __ldcs((const uint4*)(p + 1024));
    u32 Ds[8] = {lo.x, lo.y, lo.z, lo.w, hi.x, hi.y, hi.z, hi.w};
#pragma unroll
    for (int i = 0; i < 8; i++) {
      u32 t16 = h2sub(Dmin16[i], Ds[i]);  // <= 0 by construction
      float a1, b1; h2up(t16, a1, b1);
      u32 m2 = ex2h2(pkh2(a1 * ivp[i], b1 * ivg[i]));  // (Mp, Mg) packed
      float mp, mg; h2up(m2, mp, mg);
      if (i & 1) acc1 += fabsf(mp - mg); else acc0 += fabsf(mp - mg);
    }
  }
  float acc = acc0 + acc1;

  // ---------------- Per-CTA reduction (deterministic) ----------------
#pragma unroll
  for (int o = 16; o > 0; o >>= 1) acc += __shfl_down_sync(0xffffffffu, acc, o);
  __syncthreads();             // all pass-A smem use done
  float* red = (float*)smem;
  if ((tid & 31) == 0) red[tid >> 5] = acc;
  __syncthreads();
  if (tid == 0) {
    float s = 0.f;
#pragma unroll
    for (int ww = 0; ww < NTHREADS / 32; ww++) s += red[ww];
    g_partials[ctaIdx] = s;
    __threadfence();
    unsigned int old = atomicAdd(&g_count, 1u);
    red[8] = (old == NCTAS - 1) ? 1.f : 0.f;
  }
  __syncthreads();

  // ---------------- Last CTA: global reduction ----------------
  if (red[8] != 0.f) {
    __threadfence();
    float s = g_partials[tid];
    if (tid < NCTAS - NTHREADS) s += g_partials[tid + NTHREADS];
#pragma unroll
    for (int o = 16; o > 0; o >>= 1) s += __shfl_down_sync(0xffffffffu, s, o);
    __syncthreads();
    if ((tid & 31) == 0) red[tid >> 5] = s;
    __syncthreads();
    if (tid == 0) {
      float t = 0.f;
#pragma unroll
      for (int ww = 0; ww < NTHREADS / 32; ww++) t += red[ww];
      out[0] = t * (float)(1.0 / ((double)BATCH * INNER * INNER * 99.0));
      g_count = 0;   // reset for next graph replay
    }
  }
}

extern "C" void kernel_launch(void* const* d_in, const int* in_sizes, int n_in,
                              void* d_out, int out_size) {
  const float* pred = (const float*)d_in[0];
  const float* gt = (const float*)d_in[1];
  cudaFuncSetAttribute(mind_main, cudaFuncAttributeMaxDynamicSharedMemorySize,
                       SMEM_BYTES);
  dim3 grid(TILES_X, TILES_Y, BATCH);
  mind_main<<<grid, NTHREADS, SMEM_BYTES>>>(pred, gt, (float*)d_out);
}

// round 15
// speedup vs baseline: 1.9590x; 1.0224x over previous
#include <cuda_runtime.h>

// ---------------------------------------------------------------------------
// MIND loss, fused, single kernel. R15 = R14 with 512-thread CTAs:
//   same 288 CTAs / same per-CTA tile, but 2x warps per SM (16 -> 32, the
//   max) to hide LDS/barrier latency that capped issue at ~51%.
//  - row stage: 504 width-6 units (42 rows x 12 blocks), paR[12] reg cache
//  - col stage: exactly 4 rows/thread (2048 px / 512), uniform
//  - scratch: ONE uint4 per thread per slot (512*4 = 2048 = slot size)
//  - everything else as R14: fp16x2 image+buffer, +/- pair events,
//    6 conv buffers / 3 events per barrier, reverse-order __ldcs pass B
// ---------------------------------------------------------------------------

typedef unsigned int u32;

namespace {
constexpr int HIMG = 384;
constexpr int WIMG = 384;
constexpr int BATCH = 4;
constexpr int INNER = 370;          // 384 - 2*7
constexpr int TILE_H = 32;
constexpr int TILE_W = 64;
constexpr int RH = 47;              // img tile rows (q_r in [-7, 39])
constexpr int RW = 86;              // img tile cols (q_c in [-11, 74])
constexpr int IP = 87;              // img pitch in u32 (odd)
constexpr int BROWS = 42;           // buffer rows (q_r in [-3, 38])
constexpr int BP = 73;              // buffer pitch in u32 (odd)
constexpr int NTHREADS = 512;
constexpr int TILES_X = 6;
constexpr int TILES_Y = 12;
constexpr int NCTAS = BATCH * TILES_X * TILES_Y;   // 288 -> one wave @ occ 2
constexpr int NBUF = 6;             // 3 events per barrier, double-banked
constexpr int SMEM_BYTES = RH * IP * 4 + NBUF * BROWS * BP * 4;  // 89940 B
constexpr int NEVENTS = 59;         // 40 pairs + 19 singles
constexpr int NGROUPS = 20;         // ceil(59/3)
constexpr int NSLOTS = 99;          // stored D slots per pixel
constexpr int SLOT_U32 = TILE_H * TILE_W;          // 2048 per slot per CTA
constexpr size_t CTA_U32 = (size_t)NSLOTS * SLOT_U32;

constexpr double E98 = 0.32465246735834974;   // exp(-9/8)
constexpr double E48 = 0.60653065971263342;   // exp(-4/8)
constexpr double E18 = 0.88249690258459546;   // exp(-1/8)
constexpr double TPS = 25.132741228718345;    // 8*pi
constexpr float GX0 = (float)E98;
constexpr float GX1 = (float)E48;
constexpr float GX2 = (float)E18;             // center tap == 1
constexpr float GY0 = (float)(E98 / TPS);
constexpr float GY1 = (float)(E48 / TPS);
constexpr float GY2 = (float)(E18 / TPS);
constexpr float GY3 = (float)(1.0 / TPS);
constexpr float LOG2E = 1.4426950408889634f;
}  // namespace

__device__ u32 g_D[(size_t)NCTAS * CTA_U32];   // 233.6 MB scratch
__device__ float g_partials[NCTAS];
__device__ unsigned int g_count = 0;

// ---- packed f16x2 helpers ----
__device__ __forceinline__ u32 bch2(float x) {
  u32 r; asm("cvt.rn.f16x2.f32 %0,%1,%1;" : "=r"(r) : "f"(x)); return r;
}
__device__ __forceinline__ u32 pkh2(float lo, float hi) {
  u32 r; asm("cvt.rn.f16x2.f32 %0,%1,%2;" : "=r"(r) : "f"(hi), "f"(lo));
  return r;
}
__device__ __forceinline__ void h2up(u32 v, float& a, float& b) {
  asm("{\n\t.reg .b16 l,h;\n\tmov.b32 {l,h},%2;\n\t"
      "cvt.f32.f16 %0,l;\n\tcvt.f32.f16 %1,h;\n\t}"
      : "=f"(a), "=f"(b) : "r"(v));
}
__device__ __forceinline__ u32 h2mul(u32 a, u32 b) {
  u32 r; asm("mul.rn.f16x2 %0,%1,%2;" : "=r"(r) : "r"(a), "r"(b)); return r;
}
__device__ __forceinline__ u32 h2add(u32 a, u32 b) {
  u32 r; asm("add.rn.f16x2 %0,%1,%2;" : "=r"(r) : "r"(a), "r"(b)); return r;
}
__device__ __forceinline__ u32 h2fma(u32 a, u32 b, u32 c) {
  u32 r; asm("fma.rn.f16x2 %0,%1,%2,%3;" : "=r"(r) : "r"(a), "r"(b), "r"(c));
  return r;
}
__device__ __forceinline__ u32 h2min(u32 a, u32 b) {
  u32 r; asm("min.f16x2 %0,%1,%2;" : "=r"(r) : "r"(a), "r"(b)); return r;
}
__device__ __forceinline__ u32 h2sub(u32 a, u32 b) {
  u32 r; asm("sub.rn.f16x2 %0,%1,%2;" : "=r"(r) : "r"(a), "r"(b)); return r;
}
__device__ __forceinline__ u32 ex2h2(u32 x) {    // packed exp2, 1 MUFU op
  u32 r; asm("ex2.approx.f16x2 %0,%1;" : "=r"(r) : "r"(x)); return r;
}

// Event schedule. e<40: pair representatives (sy>0, or sy==0 && sx>=1);
// each also yields -s. e in [40,50): sx=-5 singles; [50,59): sy=-5 singles.
// Pair (1,0) at e=0 and (0,1) at e=8 -> V accumulates in reference order.
__device__ __forceinline__ void decode_event(int e, int& sx, int& sy,
                                             bool& pair) {
  if (e < 4)       { sx = e + 1;               sy = 0;            pair = true; }
  else if (e < 40) { int t = e - 4; sy = 1 + t / 9; sx = t % 9 - 4;
                     pair = true; }
  else if (e < 50) { sx = -5;                  sy = (e - 40) - 5; pair = false; }
  else             { sy = -5;                  sx = (e - 50) - 4; pair = false; }
}

// Fused diffsq + horizontal 7-tap conv, all f16x2. Width-6 unit, pa in regs.
__device__ __forceinline__ void produce_unit(const u32 paR[12],
                                             const u32* __restrict__ sImgH,
                                             u32* __restrict__ Bdst,
                                             int r1, int j1, int sx, int sy,
                                             u32 hx0, u32 hx1, u32 hx2) {
  const u32* pb = sImgH + (r1 + 4 - sy) * IP + (j1 + 4 - sx);
  u32 dsq[12];
#pragma unroll
  for (int k = 0; k < 12; k++) {
    u32 d = h2sub(paR[k], pb[k]);
    dsq[k] = h2mul(d, d);
  }
  u32* pr = Bdst + r1 * BP + j1;
#pragma unroll
  for (int c = 0; c < 6; c++) {
    u32 v = h2mul(hx0, dsq[c]);
    v = h2fma(hx1, dsq[c + 1], v);
    v = h2fma(hx2, dsq[c + 2], v);
    v = h2add(v, dsq[c + 3]);  // center tap weight == 1
    v = h2fma(hx2, dsq[c + 4], v);
    v = h2fma(hx1, dsq[c + 5], v);
    v = h2fma(hx0, dsq[c + 6], v);
    pr[c] = v;
  }
}

__device__ __forceinline__ u32 col7h(const u32* rv, int i,
                                     u32 hy0, u32 hy1, u32 hy2, u32 hy3) {
  u32 v = h2mul(hy0, rv[i]);
  v = h2fma(hy1, rv[i + 1], v);
  v = h2fma(hy2, rv[i + 2], v);
  v = h2fma(hy3, rv[i + 3], v);
  v = h2fma(hy2, rv[i + 4], v);
  v = h2fma(hy1, rv[i + 5], v);
  v = h2fma(hy0, rv[i + 6], v);
  return v;
}

extern "C" __global__ void __launch_bounds__(NTHREADS, 2)
mind_main(const float* __restrict__ pred, const float* __restrict__ gt,
          float* __restrict__ out) {
  extern __shared__ u32 smem[];
  u32* sImgH = smem;
  u32* bufbase = smem + RH * IP;
  u32* buf[NBUF];
#pragma unroll
  for (int i = 0; i < NBUF; i++) buf[i] = bufbase + i * BROWS * BP;

  const int tX = blockIdx.x, tY = blockIdx.y, b = blockIdx.z;
  const int tid = threadIdx.x;
  const int ctaIdx = (b * TILES_Y + tY) * TILES_X + tX;
  // One uint4 per thread per slot: slot*2048 + tid*4.
  u32* myD = g_D + (size_t)ctaIdx * CTA_U32 + tid * 4;
  const float* imgP = pred + b * HIMG * WIMG;
  const float* imgG = gt + b * HIMG * WIMG;

  // Load tile + halo (circular wrap), quantize both images to fp16x2.
  for (int i = tid; i < RH * RW; i += NTHREADS) {
    int mr = i / RW, mc = i - mr * RW;
    int gr = tY * TILE_H + mr; if (gr >= HIMG) gr -= HIMG;
    int gc = tX * TILE_W + mc - 4;
    if (gc < 0) gc += WIMG;
    if (gc >= WIMG) gc -= WIMG;
    sImgH[mr * IP + mc] = pkh2(imgP[gr * WIMG + gc], imgG[gr * WIMG + gc]);
  }
  __syncthreads();

  // Row-stage: 504 width-6 units = 42 buffer rows x 12 blocks.
  const bool rowAct = tid < 504;
  const int r1 = tid % 42;
  const int j1 = (tid / 42) * 6;

  // Cache unshifted taps (shift-invariant; reused for all 59 events).
  u32 paR[12];
  {
    const u32* pa = sImgH + (r1 + 4) * IP + (j1 + 4);
#pragma unroll
    for (int k = 0; k < 12; k++) paR[k] = pa[k];
  }

  // Col-stage: 64 cols x 8 groups of exactly 4 rows.
  const int cc = tid & 63;
  const int gg = tid >> 6;          // 0..7
  const int rbase = gg * 4;
  const int cc4 = cc + 4;           // buffer col of pixel col cc
  const bool cOK = (tX * TILE_W + cc) < INNER;
  const int py0 = tY * TILE_H + rbase;

  const u32 hx0 = bch2(GX0), hx1 = bch2(GX1), hx2 = bch2(GX2);
  const u32 hy0 = bch2(GY0), hy1 = bch2(GY1), hy2 = bch2(GY2),
            hy3 = bch2(GY3);

  u32 Dmin16[4];
  float Vp[4], Vg[4];
#pragma unroll
  for (int i = 0; i < 4; i++) {
    Dmin16[i] = 0x7BFF7BFFu;   // packed fp16 max-finite
    Vp[i] = 0.f; Vg[i] = 0.f;
  }

  // -------- Pass A: D fields -> gmem slots; Dmin + cardinal V --------
  // 6 buffers: group g consumes events {3g..3g+2} from bank (g&1)*3,
  // produces {3g+3..3g+5} into the other bank. 20 barriers.
  // Produce trim: pair event needs rows < 38+sy, single 38.
#pragma unroll
  for (int ee = 0; ee < 3; ee++) {
    int sx, sy; bool isPair;
    decode_event(ee, sx, sy, isPair);
    if (rowAct && r1 < 38 + (isPair ? sy : 0))
      produce_unit(paR, sImgH, buf[ee], r1, j1, sx, sy, hx0, hx1, hx2);
  }
  __syncthreads();

  for (int g = 0; g < NGROUPS; g++) {
    const int setc = (g & 1) * 3;
#pragma unroll
    for (int ee = 0; ee < 3; ee++) {
      const int e = 3 * g + ee;
      if (e < NEVENTS) {
        int sx, sy; bool isPair;
        decode_event(e, sx, sy, isPair);
        const u32* bc = buf[setc + ee];
        u32 rv[10];
#pragma unroll
        for (int i = 0; i < 10; i++) rv[i] = bc[(rbase + i) * BP + cc4];
        u32 D1[4];
#pragma unroll
        for (int i = 0; i < 4; i++) D1[i] = col7h(rv, i, hy0, hy1, hy2, hy3);
        ((uint4*)(myD + (size_t)e * SLOT_U32))[0] =
            make_uint4(D1[0], D1[1], D1[2], D1[3]);
        if (isPair) {
          const u32* bp2 = bc + sy * BP + sx;
#pragma unroll
          for (int i = 0; i < 10; i++) rv[i] = bp2[(rbase + i) * BP + cc4];
          u32 D2[4];
#pragma unroll
          for (int i = 0; i < 4; i++)
            D2[i] = col7h(rv, i, hy0, hy1, hy2, hy3);
          ((uint4*)(myD + (size_t)(NEVENTS + e) * SLOT_U32))[0] =
              make_uint4(D2[0], D2[1], D2[2], D2[3]);
#pragma unroll
          for (int i = 0; i < 4; i++) {
            Dmin16[i] = h2min(Dmin16[i], h2min(D1[i], D2[i]));
            if (e == 0) {            // pair (1,0): V = D(-1,0) + D(1,0)
              float p1, g1, p2, g2;
              h2up(D1[i], p1, g1); h2up(D2[i], p2, g2);
              Vp[i] = p2 + p1; Vg[i] = g2 + g1;
            } else if (e == 8) {     // pair (0,1): V = (V + D(0,-1)) + D(0,1)
              float p1, g1, p2, g2;
              h2up(D1[i], p1, g1); h2up(D2[i], p2, g2);
              Vp[i] = (Vp[i] + p2) + p1; Vg[i] = (Vg[i] + g2) + g1;
            }
          }
        } else {
#pragma unroll
          for (int i = 0; i < 4; i++) Dmin16[i] = h2min(Dmin16[i], D1[i]);
        }
      }
    }
    const int setp = ((g + 1) & 1) * 3;
#pragma unroll
    for (int ee = 0; ee < 3; ee++) {
      const int e = 3 * g + 3 + ee;
      if (e < NEVENTS) {
        int sx, sy; bool isPair;
        decode_event(e, sx, sy, isPair);
        if (rowAct && r1 < 38 + (isPair ? sy : 0))
          produce_unit(paR, sImgH, buf[setp + ee], r1, j1, sx, sy,
                       hx0, hx1, hx2);
      }
    }
    __syncthreads();
  }

  // Fold validity mask into invV: masked pixels get invV = 0 -> term 0.
  float ivp[4], ivg[4];
#pragma unroll
  for (int i = 0; i < 4; i++) {
    const bool ok = cOK && (py0 + i) < INNER;
    ivp[i] = ok ? (LOG2E / (Vp[i] * 0.25f + 1e-5f)) : 0.f;
    ivg[i] = ok ? (LOG2E / (Vg[i] * 0.25f + 1e-5f)) : 0.f;
  }

  // -------- Pass B: stream D back in TRUE reverse-write order --------
  // Write order: e=0:(slot0,slot59), ..., e=39:(slot39,slot98), then
  // singles e=40..58 -> slots 40..58. Read newest-first: 58..40, then
  // (98,39),(97,38),...,(59,0). __ldcs: evict-first (each line read once).
  // Same thread wrote these addresses -> program order, no fences.
  float acc0 = 0.f, acc1 = 0.f;
#pragma unroll 4
  for (int k = 0; k < NSLOTS; k++) {
    int slot;
    if (k < 19) {
      slot = 58 - k;                      // singles, newest first
    } else {
      int t = k - 19;
      int e = 39 - (t >> 1);
      slot = (t & 1) ? e : (NEVENTS + e); // D2 slot then D1 slot per event
    }
    uint4 v = __ldcs((const uint4*)(myD + (size_t)slot * SLOT_U32));
    u32 Ds[4] = {v.x, v.y, v.z, v.w};
#pragma unroll
    for (int i = 0; i < 4; i++) {
      u32 t16 = h2sub(Dmin16[i], Ds[i]);  // <= 0 by construction
      float a1, b1; h2up(t16, a1, b1);
      u32 m2 = ex2h2(pkh2(a1 * ivp[i], b1 * ivg[i]));  // (Mp, Mg) packed
      float mp, mg; h2up(m2, mp, mg);
      if (i & 1) acc1 += fabsf(mp - mg); else acc0 += fabsf(mp - mg);
    }
  }
  float acc = acc0 + acc1;

  // ---------------- Per-CTA reduction (deterministic) ----------------
#pragma unroll
  for (int o = 16; o > 0; o >>= 1) acc += __shfl_down_sync(0xffffffffu, acc, o);
  __syncthreads();             // all pass-A smem use done
  float* red = (float*)smem;
  if ((tid & 31) == 0) red[tid >> 5] = acc;
  __syncthreads();
  if (tid == 0) {
    float s = 0.f;
#pragma unroll
    for (int ww = 0; ww < NTHREADS / 32; ww++) s += red[ww];
    g_partials[ctaIdx] = s;
    __threadfence();
    unsigned int old = atomicAdd(&g_count, 1u);
    red[16] = (old == NCTAS - 1) ? 1.f : 0.f;
  }
  __syncthreads();

  // ---------------- Last CTA: global reduction ----------------
  if (red[16] != 0.f) {
    __threadfence();
    float s = (tid < NCTAS) ? g_partials[tid] : 0.f;
#pragma unroll
    for (int o = 16; o > 0; o >>= 1) s += __shfl_down_sync(0xffffffffu, s, o);
    __syncthreads();
    if ((tid & 31) == 0) red[tid >> 5] = s;
    __syncthreads();
    if (tid == 0) {
      float t = 0.f;
#pragma unroll
      for (int ww = 0; ww < NTHREADS / 32; ww++) t += red[ww];
      out[0] = t * (float)(1.0 / ((double)BATCH * INNER * INNER * 99.0));
      g_count = 0;   // reset for next graph replay
    }
  }
}

extern "C" void kernel_launch(void* const* d_in, const int* in_sizes, int n_in,
                              void* d_out, int out_size) {
  const float* pred = (const float*)d_in[0];
  const float* gt = (const float*)d_in[1];
  cudaFuncSetAttribute(mind_main, cudaFuncAttributeMaxDynamicSharedMemorySize,
                       SMEM_BYTES);
  dim3 grid(TILES_X, TILES_Y, BATCH);
  mind_main<<<grid, NTHREADS, SMEM_BYTES>>>(pred, gt, (float*)d_out);
}